// round 13
// baseline (speedup 1.0000x reference)
#include <cuda_runtime.h>
#include <cuda_bf16.h>
#include <math.h>
#include <stdint.h>

#define N_ 1024
#define M_ 1024
#define D_ 1024
#define G_ 16
#define DG_ 64
#define SPLITS 2

typedef unsigned long long u64;

// ---------------- scratch ----------------
__device__ float g_w[(size_t)N_ * G_ * M_];      // (N, G, M)
__device__ float g_boxA[N_ * 4];
__device__ float g_boxB[M_ * 4];
__device__ float g_trigA[N_ * 32];
__device__ float g_trigBt[32 * M_];
__device__ float g_pacc[SPLITS][(size_t)N_ * D_];
__device__ float g_pl[SPLITS][(size_t)N_ * G_];

// bf16 hi/lo operand buffers
#define MEG (1024 * 1024)
__device__ __align__(16) uint16_t g_roiH[MEG], g_roiL[MEG];
__device__ __align__(16) uint16_t g_refH[MEG], g_refL[MEG];
__device__ __align__(16) uint16_t g_wvH[MEG],  g_wvL[MEG];
__device__ __align__(16) uint16_t g_wqtH[MEG], g_wqtL[MEG];   // Wq^T [j][k]
__device__ __align__(16) uint16_t g_wktH[MEG], g_wktL[MEG];   // Wk^T [j][k]
// GEMM outputs (bf16 hi/lo), MMA-ready layouts for flash
__device__ __align__(16) uint16_t g_qbH[MEG], g_qbL[MEG];     // q [n][d]
__device__ __align__(16) uint16_t g_kbH[MEG], g_kbL[MEG];     // k [m][d]
__device__ __align__(16) uint16_t g_vtH[MEG], g_vtL[MEG];     // v^T [o][m]

// ---------------- f32x2 helpers ----------------
__device__ __forceinline__ void fma2(u64& d, u64 a, u64 b) {
    asm("fma.rn.f32x2 %0, %1, %2, %0;" : "+l"(d) : "l"(a), "l"(b));
}
__device__ __forceinline__ u64 pack2(float x, float y) {
    u64 r;
    asm("mov.b64 %0, {%1, %2};" : "=l"(r) : "f"(x), "f"(y));
    return r;
}
__device__ __forceinline__ void unpack2(u64 p, float& x, float& y) {
    asm("mov.b64 {%0, %1}, %2;" : "=f"(x), "=f"(y) : "l"(p));
}
__device__ __forceinline__ u64 dup2(float x) { return pack2(x, x); }

__device__ __forceinline__ float fast_exp(float x) {
    float t = x * 1.4426950408889634f;
    t = fminf(fmaxf(t, -120.0f), 120.0f);
    float fi = floorf(t);
    float f = t - fi;
    float p = 1.5403530393e-4f;
    p = fmaf(p, f, 1.3333558146e-3f);
    p = fmaf(p, f, 9.6181291076e-3f);
    p = fmaf(p, f, 5.5504108664e-2f);
    p = fmaf(p, f, 2.4022650696e-1f);
    p = fmaf(p, f, 6.9314718056e-1f);
    p = fmaf(p, f, 1.0f);
    return p * __int_as_float(((int)fi + 127) << 23);
}

__constant__ float c_cf[8] = {100.0f, 42.169650f, 17.782794f, 7.4989421f,
                              3.1622776f, 1.3335214f, 0.56234133f, 0.23713737f};

// ---------------- mma / bf16 helpers (baseline PTX) ----------------
__device__ __forceinline__ uint32_t smem_to_u32(const void* p) {
    uint32_t a;
    asm("{ .reg .u64 t; cvta.to.shared.u64 t, %1; cvt.u32.u64 %0, t; }" : "=r"(a) : "l"(p));
    return a;
}
__device__ __forceinline__ void mma16816(float* d, const uint32_t* a, const uint32_t* b) {
    asm volatile(
        "mma.sync.aligned.m16n8k16.row.col.f32.bf16.bf16.f32 "
        "{%0,%1,%2,%3}, {%4,%5,%6,%7}, {%8,%9}, {%0,%1,%2,%3};"
        : "+f"(d[0]), "+f"(d[1]), "+f"(d[2]), "+f"(d[3])
        : "r"(a[0]), "r"(a[1]), "r"(a[2]), "r"(a[3]), "r"(b[0]), "r"(b[1]));
}
__device__ __forceinline__ void ldsm_x4(uint32_t* r, uint32_t addr) {
    asm volatile("ldmatrix.sync.aligned.m8n8.x4.shared.b16 {%0,%1,%2,%3}, [%4];"
                 : "=r"(r[0]), "=r"(r[1]), "=r"(r[2]), "=r"(r[3]) : "r"(addr));
}
__device__ __forceinline__ void ldsm_x2(uint32_t* r, uint32_t addr) {
    asm volatile("ldmatrix.sync.aligned.m8n8.x2.shared.b16 {%0,%1}, [%2];"
                 : "=r"(r[0]), "=r"(r[1]) : "r"(addr));
}
__device__ __forceinline__ void cp16(uint32_t saddr, const void* gptr) {
    asm volatile("cp.async.cg.shared.global [%0], [%1], 16;" :: "r"(saddr), "l"(gptr));
}
#define CP_COMMIT() asm volatile("cp.async.commit_group;" ::: "memory")
#define SWZ(bo) ((bo) ^ (((bo) >> 3) & 0x70))

// pack (lo, hi) floats -> bf16x2 register (lo in bits [0:16))
__device__ __forceinline__ uint32_t cvt2bf(float lo, float hi) {
    uint32_t r;
    asm("cvt.rn.satfinite.bf16x2.f32 %0, %1, %2;" : "=r"(r) : "f"(hi), "f"(lo));
    return r;
}
__device__ __forceinline__ float bflo(uint32_t p) { return __uint_as_float(p << 16); }
__device__ __forceinline__ float bfhi(uint32_t p) { return __uint_as_float(p & 0xFFFF0000u); }

// ---------------- box prep ----------------
__global__ void box_prep(const float* __restrict__ rois1, const float* __restrict__ rois2) {
    int i = blockIdx.x * blockDim.x + threadIdx.x;
    if (i >= N_) return;
    {
        float xmin = rois1[i*4+0], ymin = rois1[i*4+1], xmax = rois1[i*4+2], ymax = rois1[i*4+3];
        float w = xmax - xmin + 1.0f, h = ymax - ymin + 1.0f;
        g_boxA[i*4+0] = 0.5f*(xmin+xmax); g_boxA[i*4+1] = 0.5f*(ymin+ymax);
        g_boxA[i*4+2] = 1.0f/w;           g_boxA[i*4+3] = 1.0f/h;
        float lw = logf(w), lh = logf(h);
#pragma unroll
        for (int f = 0; f < 8; f++) {
            float s, c;
            sincosf(lw * c_cf[f], &s, &c);
            g_trigA[i*32 + f] = s;      g_trigA[i*32 + 8 + f] = c;
            sincosf(lh * c_cf[f], &s, &c);
            g_trigA[i*32 + 16 + f] = s; g_trigA[i*32 + 24 + f] = c;
        }
    }
    {
        float xmin = rois2[i*4+0], ymin = rois2[i*4+1], xmax = rois2[i*4+2], ymax = rois2[i*4+3];
        float w = xmax - xmin + 1.0f, h = ymax - ymin + 1.0f;
        g_boxB[i*4+0] = 0.5f*(xmin+xmax); g_boxB[i*4+1] = 0.5f*(ymin+ymax);
        g_boxB[i*4+2] = 1.0f/w;           g_boxB[i*4+3] = 1.0f/h;
        float lw = logf(w), lh = logf(h);
#pragma unroll
        for (int f = 0; f < 8; f++) {
            float s, c;
            sincosf(lw * c_cf[f], &s, &c);
            g_trigBt[f*M_ + i] = s;        g_trigBt[(8+f)*M_ + i] = c;
            sincosf(lh * c_cf[f], &s, &c);
            g_trigBt[(16+f)*M_ + i] = s;   g_trigBt[(24+f)*M_ + i] = c;
        }
    }
}

// ---------------- fp32 -> bf16 hi/lo (row-major tensors) ----------------
__global__ __launch_bounds__(256) void conv_a(const float* __restrict__ roi,
                                              const float* __restrict__ ref,
                                              const float* __restrict__ wv) {
    const int z = blockIdx.y;
    const float4* src = (const float4*)(z == 0 ? roi : z == 1 ? ref : wv);
    uint2* dh = (uint2*)(z == 0 ? g_roiH : z == 1 ? g_refH : g_wvH);
    uint2* dl = (uint2*)(z == 0 ? g_roiL : z == 1 ? g_refL : g_wvL);
    int i = blockIdx.x * 256 + threadIdx.x;
    float4 x = src[i];
    uint32_t h01 = cvt2bf(x.x, x.y), h23 = cvt2bf(x.z, x.w);
    float l0 = x.x - bflo(h01), l1 = x.y - bfhi(h01);
    float l2 = x.z - bflo(h23), l3 = x.w - bfhi(h23);
    dh[i] = make_uint2(h01, h23);
    dl[i] = make_uint2(cvt2bf(l0, l1), cvt2bf(l2, l3));
}

// ---------------- Wq/Wk transpose + bf16 hi/lo: W[k][j] -> Wt[j][k] ----------------
__global__ __launch_bounds__(256) void conv_w(const float* __restrict__ Wq,
                                              const float* __restrict__ Wk) {
    __shared__ float ts[64][65];
    const int z = blockIdx.z;
    const float* W = z ? Wk : Wq;
    uint2* dh = (uint2*)(z ? g_wktH : g_wqtH);
    uint2* dl = (uint2*)(z ? g_wktL : g_wqtL);
    const int j0 = blockIdx.x * 64, k0 = blockIdx.y * 64;
    const int t = threadIdx.x;
#pragma unroll
    for (int it = 0; it < 4; it++) {
        int lin = it * 256 + t;
        int k = lin >> 4, j4 = (lin & 15) << 2;
        float4 v = *(const float4*)&W[(size_t)(k0 + k) * D_ + j0 + j4];
        ts[j4 + 0][k] = v.x; ts[j4 + 1][k] = v.y; ts[j4 + 2][k] = v.z; ts[j4 + 3][k] = v.w;
    }
    __syncthreads();
#pragma unroll
    for (int it = 0; it < 4; it++) {
        int lin = it * 256 + t;
        int j = lin >> 4, k4 = (lin & 15) << 2;
        float a = ts[j][k4 + 0], b = ts[j][k4 + 1], c = ts[j][k4 + 2], d = ts[j][k4 + 3];
        uint32_t h01 = cvt2bf(a, b), h23 = cvt2bf(c, d);
        float l0 = a - bflo(h01), l1 = b - bfhi(h01);
        float l2 = c - bflo(h23), l3 = d - bfhi(h23);
        size_t idx = ((size_t)(j0 + j) * D_ + k0 + k4) >> 2;
        dh[idx] = make_uint2(h01, h23);
        dl[idx] = make_uint2(cvt2bf(l0, l1), cvt2bf(l2, l3));
    }
}

// ---------------- tc_gemm body (round-11 version: 128m x 64n tiles) ----------------
#define OFF_AH 0
#define OFF_AL 16384
#define OFF_BH 32768
#define OFF_BL 40960
#define STAGE_BYTES 49152
#define TC_SMEM (2 * STAGE_BYTES)   // 98304

__device__ __forceinline__ void tc_gemm_body(char* smem, int jb, int ib, int mat,
                                             const float* __restrict__ bq,
                                             const float* __restrict__ bk) {
    const uint32_t sb = smem_to_u32(smem);
    const int t = threadIdx.x;
    const int wid = t >> 5, lane = t & 31;
    const int j0 = jb * 64, i0 = ib * 128;

    const uint16_t* Ah;
    const uint16_t* Al;
    const uint16_t* Bh;
    const uint16_t* Bl;
    if (mat == 0)      { Ah = g_roiH; Al = g_roiL; Bh = g_wqtH; Bl = g_wqtL; }
    else if (mat == 1) { Ah = g_refH; Al = g_refL; Bh = g_wktH; Bl = g_wktL; }
    else               { Ah = g_refH; Al = g_refL; Bh = g_wvH;  Bl = g_wvL; }

    const int wm = wid & 3, wn = wid >> 2;
    const int lr = lane & 7, lq = lane >> 3;

    float d[2][4][4];
#pragma unroll
    for (int a = 0; a < 2; a++)
#pragma unroll
        for (int b = 0; b < 4; b++)
#pragma unroll
            for (int c = 0; c < 4; c++) d[a][b][c] = 0.0f;

    const uint32_t a_off0 = (uint32_t)((wm*32 + (lq & 1)*8 + lr) * 128 + (lq >> 1) * 16);
    const uint32_t b_off0 = (uint32_t)((wn*32 + lr) * 128 + (lq & 1) * 16);

    auto loadChunk = [&](int ch, int stage) {
        const uint32_t sbase = sb + stage * STAGE_BYTES;
        {
            int row = t >> 1;
#pragma unroll
            for (int uu = 0; uu < 4; uu++) {
                int u = (t & 1) * 4 + uu;
                uint32_t so = SWZ((uint32_t)(row * 128 + u * 16));
                cp16(sbase + OFF_AH + so, Ah + ((size_t)(i0 + row) * 1024 + ch * 64 + u * 8));
                cp16(sbase + OFF_AL + so, Al + ((size_t)(i0 + row) * 1024 + ch * 64 + u * 8));
            }
        }
        {
            int row = t >> 2;
#pragma unroll
            for (int uu = 0; uu < 2; uu++) {
                int u = (t & 3) * 2 + uu;
                uint32_t so = SWZ((uint32_t)(row * 128 + u * 16));
                cp16(sbase + OFF_BH + so, Bh + ((size_t)(j0 + row) * 1024 + ch * 64 + u * 8));
                cp16(sbase + OFF_BL + so, Bl + ((size_t)(j0 + row) * 1024 + ch * 64 + u * 8));
            }
        }
    };

    loadChunk(0, 0);
    CP_COMMIT();

    for (int ch = 0; ch < 16; ch++) {
        if (ch + 1 < 16) {
            loadChunk(ch + 1, (ch + 1) & 1);
            CP_COMMIT();
            asm volatile("cp.async.wait_group 1;" ::: "memory");
        } else {
            asm volatile("cp.async.wait_group 0;" ::: "memory");
        }
        __syncthreads();

        const uint32_t st = sb + (ch & 1) * STAGE_BYTES;
#pragma unroll
        for (int ks = 0; ks < 4; ks++) {
            const uint32_t kb = (uint32_t)(ks * 32);
            uint32_t ah[2][4], al[2][4], bh[4][2], bl[4][2];
#pragma unroll
            for (int ma = 0; ma < 2; ma++) {
                uint32_t off = SWZ(a_off0 + (uint32_t)(ma * 16 * 128) + kb);
                ldsm_x4(ah[ma], st + OFF_AH + off);
                ldsm_x4(al[ma], st + OFF_AL + off);
            }
#pragma unroll
            for (int na = 0; na < 4; na++) {
                uint32_t off = SWZ(b_off0 + (uint32_t)(na * 8 * 128) + kb);
                ldsm_x2(bh[na], st + OFF_BH + off);
                ldsm_x2(bl[na], st + OFF_BL + off);
            }
#pragma unroll
            for (int ma = 0; ma < 2; ma++)
#pragma unroll
                for (int na = 0; na < 4; na++)
                    mma16816(d[ma][na], ah[ma], bh[na]);
#pragma unroll
            for (int ma = 0; ma < 2; ma++)
#pragma unroll
                for (int na = 0; na < 4; na++)
                    mma16816(d[ma][na], ah[ma], bl[na]);
#pragma unroll
            for (int ma = 0; ma < 2; ma++)
#pragma unroll
                for (int na = 0; na < 4; na++)
                    mma16816(d[ma][na], al[ma], bh[na]);
        }
        __syncthreads();
    }

    // stage D in smem: sd[128 i][68] cols j
    float* sd = (float*)smem;
    const int gid = lane >> 2, tig = lane & 3;
#pragma unroll
    for (int ma = 0; ma < 2; ma++)
#pragma unroll
        for (int na = 0; na < 4; na++) {
            int row = wm * 32 + ma * 16 + gid;
            int col = wn * 32 + na * 8 + 2 * tig;
            sd[row * 68 + col]           = d[ma][na][0];
            sd[row * 68 + col + 1]       = d[ma][na][1];
            sd[(row + 8) * 68 + col]     = d[ma][na][2];
            sd[(row + 8) * 68 + col + 1] = d[ma][na][3];
        }
    __syncthreads();

    if (mat != 2) {
        const float* bias = (mat == 0) ? bq : bk;
        uint16_t* dH = (mat == 0) ? g_qbH : g_kbH;
        uint16_t* dL = (mat == 0) ? g_qbL : g_kbL;
        int i = t >> 1, jh = (t & 1) * 32;
#pragma unroll
        for (int jj = 0; jj < 32; jj += 4) {
            float4 v = *(const float4*)&sd[i * 68 + jh + jj];
            float4 bb = *(const float4*)&bias[j0 + jh + jj];
            v.x += bb.x; v.y += bb.y; v.z += bb.z; v.w += bb.w;
            uint32_t h01 = cvt2bf(v.x, v.y), h23 = cvt2bf(v.z, v.w);
            float l0 = v.x - bflo(h01), l1 = v.y - bfhi(h01);
            float l2 = v.z - bflo(h23), l3 = v.w - bfhi(h23);
            size_t off = (size_t)(i0 + i) * 1024 + j0 + jh + jj;
            *(uint2*)&dH[off] = make_uint2(h01, h23);
            *(uint2*)&dL[off] = make_uint2(cvt2bf(l0, l1), cvt2bf(l2, l3));
        }
    } else {
        int j = t >> 2, ih = (t & 3) * 32;
#pragma unroll
        for (int mm = 0; mm < 32; mm += 4) {
            float v0 = sd[(ih + mm + 0) * 68 + j];
            float v1 = sd[(ih + mm + 1) * 68 + j];
            float v2 = sd[(ih + mm + 2) * 68 + j];
            float v3 = sd[(ih + mm + 3) * 68 + j];
            uint32_t h01 = cvt2bf(v0, v1), h23 = cvt2bf(v2, v3);
            float l0 = v0 - bflo(h01), l1 = v1 - bfhi(h01);
            float l2 = v2 - bflo(h23), l3 = v3 - bfhi(h23);
            size_t off = (size_t)(j0 + j) * 1024 + i0 + ih + mm;
            *(uint2*)&g_vtH[off] = make_uint2(h01, h23);
            *(uint2*)&g_vtL[off] = make_uint2(cvt2bf(l0, l1), cvt2bf(l2, l3));
        }
    }
}

// ---------------- posw body ----------------
__device__ __forceinline__ void posw_body(int bx_p, int n,
                                          const float* __restrict__ Wg,
                                          const float* __restrict__ bg) {
    __shared__ float wgt[64][16];
    __shared__ float bgs[G_];
    const int t = threadIdx.x;
#pragma unroll
    for (int i = t; i < 1024; i += 256) {
        int g = i >> 6, e = i & 63;
        wgt[e][g] = Wg[i];
    }
    if (t < G_) bgs[t] = bg[t];
    __syncthreads();

    const int m0 = bx_p * 512 + t;
    const int m1 = m0 + 256;

    u64 acc0[8], acc1[8];
#pragma unroll
    for (int gp = 0; gp < 8; gp++) {
        u64 b2 = pack2(bgs[2*gp], bgs[2*gp+1]);
        acc0[gp] = b2;
        acc1[gp] = b2;
    }

    auto upd = [&](int e, float v0, float v1) {
        const ulonglong2* wr = (const ulonglong2*)&wgt[e][0];
        ulonglong2 wa = wr[0], wb = wr[1];
        u64 d0 = dup2(v0), d1 = dup2(v1);
        fma2(acc0[0], d0, wa.x); fma2(acc1[0], d1, wa.x);
        fma2(acc0[1], d0, wa.y); fma2(acc1[1], d1, wa.y);
        fma2(acc0[2], d0, wb.x); fma2(acc1[2], d1, wb.x);
        fma2(acc0[3], d0, wb.y); fma2(acc1[3], d1, wb.y);
        ulonglong2 wc = wr[2], wd = wr[3];
        fma2(acc0[4], d0, wc.x); fma2(acc1[4], d1, wc.x);
        fma2(acc0[5], d0, wc.y); fma2(acc1[5], d1, wc.y);
        fma2(acc0[6], d0, wd.x); fma2(acc1[6], d1, wd.x);
        fma2(acc0[7], d0, wd.y); fma2(acc1[7], d1, wd.y);
    };

    const float4 bn = *(const float4*)&g_boxA[n * 4];
    const float4 bm0 = *(const float4*)&g_boxB[m0 * 4];
    const float4 bm1 = *(const float4*)&g_boxB[m1 * 4];

    {
        float px0 = __logf(fabsf(bn.x - bm0.x) * bn.z + 1e-3f);
        float px1 = __logf(fabsf(bn.x - bm1.x) * bn.z + 1e-3f);
#pragma unroll
        for (int f = 0; f < 8; f++) {
            float s0, c0, s1, c1;
            __sincosf(px0 * c_cf[f], &s0, &c0);
            __sincosf(px1 * c_cf[f], &s1, &c1);
            upd(f, s0, s1);
            upd(8 + f, c0, c1);
        }
        float py0 = __logf(fabsf(bn.y - bm0.y) * bn.w + 1e-3f);
        float py1 = __logf(fabsf(bn.y - bm1.y) * bn.w + 1e-3f);
#pragma unroll
        for (int f = 0; f < 8; f++) {
            float s0, c0, s1, c1;
            __sincosf(py0 * c_cf[f], &s0, &c0);
            __sincosf(py1 * c_cf[f], &s1, &c1);
            upd(16 + f, s0, s1);
            upd(24 + f, c0, c1);
        }
    }

#pragma unroll
    for (int f = 0; f < 8; f++) {
        float snf = g_trigA[n*32 + f], cnf = g_trigA[n*32 + 8 + f];
        float sm0 = g_trigBt[f*M_ + m0], cm0 = g_trigBt[(8+f)*M_ + m0];
        float sm1 = g_trigBt[f*M_ + m1], cm1 = g_trigBt[(8+f)*M_ + m1];
        upd(32 + f, snf*cm0 - cnf*sm0, snf*cm1 - cnf*sm1);
        upd(40 + f, fmaf(cnf, cm0, snf*sm0), fmaf(cnf, cm1, snf*sm1));
    }
#pragma unroll
    for (int f = 0; f < 8; f++) {
        float snf = g_trigA[n*32 + 16 + f], cnf = g_trigA[n*32 + 24 + f];
        float sm0 = g_trigBt[(16+f)*M_ + m0], cm0 = g_trigBt[(24+f)*M_ + m0];
        float sm1 = g_trigBt[(16+f)*M_ + m1], cm1 = g_trigBt[(24+f)*M_ + m1];
        upd(48 + f, snf*cm0 - cnf*sm0, snf*cm1 - cnf*sm1);
        upd(56 + f, fmaf(cnf, cm0, snf*sm0), fmaf(cnf, cm1, snf*sm1));
    }

    const size_t base = (size_t)n * G_ * M_;
#pragma unroll
    for (int gp = 0; gp < 8; gp++) {
        float x0, y0, x1, y1;
        unpack2(acc0[gp], x0, y0);
        unpack2(acc1[gp], x1, y1);
        g_w[base + (size_t)(2*gp)   * M_ + m0] = fmaxf(x0, 0.0f) + 1e-6f;
        g_w[base + (size_t)(2*gp+1) * M_ + m0] = fmaxf(y0, 0.0f) + 1e-6f;
        g_w[base + (size_t)(2*gp)   * M_ + m1] = fmaxf(x1, 0.0f) + 1e-6f;
        g_w[base + (size_t)(2*gp+1) * M_ + m1] = fmaxf(y1, 0.0f) + 1e-6f;
    }
}

// ---------------- fused middle kernel: gemm blocks + posw blocks interleaved ----------------
// grid = 2432 = 19*128; B%19 in [0,3) -> gemm (384 blocks), else posw (2048 blocks).
__global__ __launch_bounds__(256, 2) void fused_mid(const float* __restrict__ bq,
                                                    const float* __restrict__ bk,
                                                    const float* __restrict__ Wg,
                                                    const float* __restrict__ bg) {
    extern __shared__ char smem[];
    const int B = blockIdx.x;
    const int grp = B / 19, rem = B % 19;
    if (rem < 3) {
        int gidx = grp * 3 + rem;             // 0..383
        int jb = gidx & 15;
        int ib = (gidx >> 4) & 7;
        int mat = gidx >> 7;
        tc_gemm_body(smem, jb, ib, mat, bq, bk);
    } else {
        int pidx = grp * 16 + (rem - 3);      // 0..2047
        posw_body(pidx & 1, pidx >> 1, Wg, bg);
    }
}

// ---------------- flash on tensor cores (round-11, unchanged) ----------------
#define FQ_H 0
#define FQ_L 16384
#define FSTG 32768
#define FS_KH 0
#define FS_KL 8192
#define FS_VH 16384
#define FS_VL 24576
#define FSTG_BYTES 32768
#define FLASH_SMEM (32768 + 2 * 32768)   // 98304

__global__ __launch_bounds__(256, 2) void flash_kernel() {
    extern __shared__ char smem[];
    const uint32_t sb = smem_to_u32(smem);
    const int t = threadIdx.x;
    const int wid = t >> 5, lane = t & 31;
    const int lr = lane & 7, lq = lane >> 3;
    const int gid = lane >> 2, tig = lane & 3;
    const int g = blockIdx.y;
    const int n0 = blockIdx.x * 128;
    const int z = blockIdx.z;

    const uint32_t a_off0 = (uint32_t)((wid*16 + (lq & 1)*8 + lr) * 128 + (lq >> 1) * 16);
    const uint32_t b_off0 = (uint32_t)(lr * 128 + (lq & 1) * 16);

    {
        int row = t >> 1;
#pragma unroll
        for (int uu = 0; uu < 4; uu++) {
            int u = (t & 1) * 4 + uu;
            uint32_t so = SWZ((uint32_t)(row * 128 + u * 16));
            cp16(sb + FQ_H + so, g_qbH + ((size_t)(n0 + row) * 1024 + g * 64 + u * 8));
            cp16(sb + FQ_L + so, g_qbL + ((size_t)(n0 + row) * 1024 + g * 64 + u * 8));
        }
    }
    auto loadStage = [&](int it, int stg) {
        const uint32_t sbase = sb + FSTG + stg * FSTG_BYTES;
        const int m0 = z * 512 + it * 64;
        int row = t >> 2;
#pragma unroll
        for (int uu = 0; uu < 2; uu++) {
            int u = (t & 3) * 2 + uu;
            uint32_t so = SWZ((uint32_t)(row * 128 + u * 16));
            cp16(sbase + FS_KH + so, g_kbH + ((size_t)(m0 + row) * 1024 + g * 64 + u * 8));
            cp16(sbase + FS_KL + so, g_kbL + ((size_t)(m0 + row) * 1024 + g * 64 + u * 8));
            cp16(sbase + FS_VH + so, g_vtH + ((size_t)(g * 64 + row) * 1024 + m0 + u * 8));
            cp16(sbase + FS_VL + so, g_vtL + ((size_t)(g * 64 + row) * 1024 + m0 + u * 8));
        }
    };

    loadStage(0, 0);
    CP_COMMIT();

    float o_[8][4];
#pragma unroll
    for (int a = 0; a < 8; a++)
#pragma unroll
        for (int b = 0; b < 4; b++) o_[a][b] = 0.0f;
    float lr0 = 0.0f, lr1 = 0.0f;

    for (int it = 0; it < 8; it++) {
        if (it + 1 < 8) {
            loadStage(it + 1, (it + 1) & 1);
            CP_COMMIT();
            asm volatile("cp.async.wait_group 1;" ::: "memory");
        } else {
            asm volatile("cp.async.wait_group 0;" ::: "memory");
        }
        __syncthreads();

        const uint32_t st = sb + FSTG + (it & 1) * FSTG_BYTES;
        const int m0 = z * 512 + it * 64;

        float s[8][4];
#pragma unroll
        for (int a = 0; a < 8; a++)
#pragma unroll
            for (int b = 0; b < 4; b++) s[a][b] = 0.0f;

#pragma unroll
        for (int dc = 0; dc < 4; dc++) {
            uint32_t aoff = SWZ(a_off0 + (uint32_t)(dc * 32));
            uint32_t aqh[4], aql[4];
            ldsm_x4(aqh, sb + FQ_H + aoff);
            ldsm_x4(aql, sb + FQ_L + aoff);
#pragma unroll
            for (int mt = 0; mt < 8; mt++) {
                uint32_t boff = SWZ(b_off0 + (uint32_t)(mt * 8 * 128 + dc * 32));
                uint32_t bkh[2], bkl[2];
                ldsm_x2(bkh, st + FS_KH + boff);
                ldsm_x2(bkl, st + FS_KL + boff);
                mma16816(s[mt], aqh, bkh);
                mma16816(s[mt], aqh, bkl);
                mma16816(s[mt], aql, bkh);
            }
        }

        uint32_t paH[4][4], paL[4][4];
        const size_t wbase0 = ((size_t)(n0 + wid * 16 + gid) * G_ + g) * M_;
        const size_t wbase1 = wbase0 + (size_t)8 * G_ * M_;
#pragma unroll
        for (int mt = 0; mt < 8; mt++) {
            int mcol = m0 + mt * 8 + 2 * tig;
            float2 w0 = *(const float2*)&g_w[wbase0 + mcol];
            float2 w1 = *(const float2*)&g_w[wbase1 + mcol];
            float p0 = w0.x * fast_exp(s[mt][0] * 0.125f);
            float p1 = w0.y * fast_exp(s[mt][1] * 0.125f);
            float p2 = w1.x * fast_exp(s[mt][2] * 0.125f);
            float p3 = w1.y * fast_exp(s[mt][3] * 0.125f);
            lr0 += p0 + p1;
            lr1 += p2 + p3;
            uint32_t h01 = cvt2bf(p0, p1), h23 = cvt2bf(p2, p3);
            float l0 = p0 - bflo(h01), l1 = p1 - bfhi(h01);
            float l2 = p2 - bflo(h23), l3 = p3 - bfhi(h23);
            int kc = mt >> 1, hf = (mt & 1) * 2;
            paH[kc][hf + 0] = h01;
            paH[kc][hf + 1] = h23;
            paL[kc][hf + 0] = cvt2bf(l0, l1);
            paL[kc][hf + 1] = cvt2bf(l2, l3);
        }

#pragma unroll
        for (int kc = 0; kc < 4; kc++) {
#pragma unroll
            for (int ot = 0; ot < 8; ot++) {
                uint32_t boff = SWZ(b_off0 + (uint32_t)(ot * 8 * 128 + kc * 32));
                uint32_t bvh[2], bvl[2];
                ldsm_x2(bvh, st + FS_VH + boff);
                ldsm_x2(bvl, st + FS_VL + boff);
                mma16816(o_[ot], paH[kc], bvh);
                mma16816(o_[ot], paH[kc], bvl);
                mma16816(o_[ot], paL[kc], bvh);
            }
        }
        __syncthreads();
    }

    lr0 += __shfl_xor_sync(0xffffffffu, lr0, 1);
    lr0 += __shfl_xor_sync(0xffffffffu, lr0, 2);
    lr1 += __shfl_xor_sync(0xffffffffu, lr1, 1);
    lr1 += __shfl_xor_sync(0xffffffffu, lr1, 2);

    const int r0 = n0 + wid * 16 + gid;
    if (tig == 0) {
        g_pl[z][(size_t)r0 * G_ + g] = lr0;
        g_pl[z][(size_t)(r0 + 8) * G_ + g] = lr1;
    }
#pragma unroll
    for (int ot = 0; ot < 8; ot++) {
        int col = g * 64 + ot * 8 + 2 * tig;
        *(float2*)&g_pacc[z][(size_t)r0 * D_ + col] = make_float2(o_[ot][0], o_[ot][1]);
        *(float2*)&g_pacc[z][(size_t)(r0 + 8) * D_ + col] = make_float2(o_[ot][2], o_[ot][3]);
    }
}

// ---------------- combine partials ----------------
__global__ __launch_bounds__(256) void reduce_kernel(const float* __restrict__ bv,
                                                     float* __restrict__ out) {
    int idx = blockIdx.x * 256 + threadIdx.x;
    int n = idx >> 8;
    int col = (idx & 255) << 2;
    int g = col >> 6;
    float l = 0.0f;
    float4 a = make_float4(0.f, 0.f, 0.f, 0.f);
#pragma unroll
    for (int zz = 0; zz < SPLITS; zz++) {
        l += g_pl[zz][(size_t)n * G_ + g];
        float4 p = *(const float4*)&g_pacc[zz][(size_t)n * D_ + col];
        a.x += p.x; a.y += p.y; a.z += p.z; a.w += p.w;
    }
    float inv = 1.0f / l;
    float4 b4 = *(const float4*)&bv[col];
    float4 o;
    o.x = fmaf(a.x, inv, b4.x);
    o.y = fmaf(a.y, inv, b4.y);
    o.z = fmaf(a.z, inv, b4.z);
    o.w = fmaf(a.w, inv, b4.w);
    *(float4*)&out[(size_t)n * D_ + col] = o;
}

// ---------------- host launcher ----------------
extern "C" void kernel_launch(void* const* d_in, const int* in_sizes, int n_in,
                              void* d_out, int out_size) {
    const float* roi   = (const float*)d_in[0];
    const float* ref   = (const float*)d_in[1];
    const float* rois1 = (const float*)d_in[2];
    const float* rois2 = (const float*)d_in[3];
    const float* Wq    = (const float*)d_in[4];
    const float* bq    = (const float*)d_in[5];
    const float* Wk    = (const float*)d_in[6];
    const float* bk    = (const float*)d_in[7];
    const float* Wg    = (const float*)d_in[8];
    const float* bg    = (const float*)d_in[9];
    const float* Wv    = (const float*)d_in[10];
    const float* bv    = (const float*)d_in[11];
    float* out = (float*)d_out;

    static bool attr_set = false;
    if (!attr_set) {
        cudaFuncSetAttribute(flash_kernel, cudaFuncAttributeMaxDynamicSharedMemorySize, FLASH_SMEM);
        cudaFuncSetAttribute(fused_mid, cudaFuncAttributeMaxDynamicSharedMemorySize, TC_SMEM);
        attr_set = true;
    }

    box_prep<<<4, 256>>>(rois1, rois2);
    conv_a<<<dim3(1024, 3), 256>>>(roi, ref, Wv);
    conv_w<<<dim3(16, 16, 2), 256>>>(Wq, Wk);
    fused_mid<<<2432, 256, TC_SMEM>>>(bq, bk, Wg, bg);
    flash_kernel<<<dim3(8, 16, 2), 256, FLASH_SMEM>>>();
    reduce_kernel<<<1024, 256>>>(bv, out);
}

// round 14
// speedup vs baseline: 1.2679x; 1.2679x over previous
#include <cuda_runtime.h>
#include <cuda_bf16.h>
#include <math.h>
#include <stdint.h>

#define N_ 1024
#define M_ 1024
#define D_ 1024
#define G_ 16
#define DG_ 64
#define SPLITS 2

typedef unsigned long long u64;

// ---------------- scratch ----------------
__device__ float g_w[(size_t)N_ * G_ * M_];      // (N, G, M)
__device__ float g_boxA[N_ * 4];
__device__ float g_boxB[M_ * 4];
__device__ float g_trigA[N_ * 32];
__device__ float g_trigBt[32 * M_];
__device__ float g_pacc[SPLITS][(size_t)N_ * D_];
__device__ float g_pl[SPLITS][(size_t)N_ * G_];

// bf16 hi/lo operand buffers
#define MEG (1024 * 1024)
__device__ __align__(16) uint16_t g_roiH[MEG], g_roiL[MEG];
__device__ __align__(16) uint16_t g_refH[MEG], g_refL[MEG];
__device__ __align__(16) uint16_t g_wvH[MEG],  g_wvL[MEG];
__device__ __align__(16) uint16_t g_wqtH[MEG], g_wqtL[MEG];   // Wq^T [j][k]
__device__ __align__(16) uint16_t g_wktH[MEG], g_wktL[MEG];   // Wk^T [j][k]
// GEMM outputs (bf16 hi/lo), MMA-ready layouts for flash
__device__ __align__(16) uint16_t g_qbH[MEG], g_qbL[MEG];     // q [n][d]
__device__ __align__(16) uint16_t g_kbH[MEG], g_kbL[MEG];     // k [m][d]
__device__ __align__(16) uint16_t g_vtH[MEG], g_vtL[MEG];     // v^T [o][m]

// ---------------- f32x2 helpers ----------------
__device__ __forceinline__ void fma2(u64& d, u64 a, u64 b) {
    asm("fma.rn.f32x2 %0, %1, %2, %0;" : "+l"(d) : "l"(a), "l"(b));
}
__device__ __forceinline__ u64 pack2(float x, float y) {
    u64 r;
    asm("mov.b64 %0, {%1, %2};" : "=l"(r) : "f"(x), "f"(y));
    return r;
}
__device__ __forceinline__ void unpack2(u64 p, float& x, float& y) {
    asm("mov.b64 {%0, %1}, %2;" : "=f"(x), "=f"(y) : "l"(p));
}
__device__ __forceinline__ u64 dup2(float x) { return pack2(x, x); }

__device__ __forceinline__ float fast_exp(float x) {
    float t = x * 1.4426950408889634f;
    t = fminf(fmaxf(t, -120.0f), 120.0f);
    float fi = floorf(t);
    float f = t - fi;
    float p = 1.5403530393e-4f;
    p = fmaf(p, f, 1.3333558146e-3f);
    p = fmaf(p, f, 9.6181291076e-3f);
    p = fmaf(p, f, 5.5504108664e-2f);
    p = fmaf(p, f, 2.4022650696e-1f);
    p = fmaf(p, f, 6.9314718056e-1f);
    p = fmaf(p, f, 1.0f);
    return p * __int_as_float(((int)fi + 127) << 23);
}

__constant__ float c_cf[8] = {100.0f, 42.169650f, 17.782794f, 7.4989421f,
                              3.1622776f, 1.3335214f, 0.56234133f, 0.23713737f};

// ---------------- mma / bf16 helpers (baseline PTX) ----------------
__device__ __forceinline__ uint32_t smem_to_u32(const void* p) {
    uint32_t a;
    asm("{ .reg .u64 t; cvta.to.shared.u64 t, %1; cvt.u32.u64 %0, t; }" : "=r"(a) : "l"(p));
    return a;
}
__device__ __forceinline__ void mma16816(float* d, const uint32_t* a, const uint32_t* b) {
    asm volatile(
        "mma.sync.aligned.m16n8k16.row.col.f32.bf16.bf16.f32 "
        "{%0,%1,%2,%3}, {%4,%5,%6,%7}, {%8,%9}, {%0,%1,%2,%3};"
        : "+f"(d[0]), "+f"(d[1]), "+f"(d[2]), "+f"(d[3])
        : "r"(a[0]), "r"(a[1]), "r"(a[2]), "r"(a[3]), "r"(b[0]), "r"(b[1]));
}
__device__ __forceinline__ void ldsm_x4(uint32_t* r, uint32_t addr) {
    asm volatile("ldmatrix.sync.aligned.m8n8.x4.shared.b16 {%0,%1,%2,%3}, [%4];"
                 : "=r"(r[0]), "=r"(r[1]), "=r"(r[2]), "=r"(r[3]) : "r"(addr));
}
__device__ __forceinline__ void ldsm_x2(uint32_t* r, uint32_t addr) {
    asm volatile("ldmatrix.sync.aligned.m8n8.x2.shared.b16 {%0,%1}, [%2];"
                 : "=r"(r[0]), "=r"(r[1]) : "r"(addr));
}
__device__ __forceinline__ void cp16(uint32_t saddr, const void* gptr) {
    asm volatile("cp.async.cg.shared.global [%0], [%1], 16;" :: "r"(saddr), "l"(gptr));
}
#define CP_COMMIT() asm volatile("cp.async.commit_group;" ::: "memory")
#define SWZ(bo) ((bo) ^ (((bo) >> 3) & 0x70))

// pack (lo, hi) floats -> bf16x2 register (lo in bits [0:16))
__device__ __forceinline__ uint32_t cvt2bf(float lo, float hi) {
    uint32_t r;
    asm("cvt.rn.satfinite.bf16x2.f32 %0, %1, %2;" : "=r"(r) : "f"(hi), "f"(lo));
    return r;
}
__device__ __forceinline__ float bflo(uint32_t p) { return __uint_as_float(p << 16); }
__device__ __forceinline__ float bfhi(uint32_t p) { return __uint_as_float(p & 0xFFFF0000u); }

// ---------------- box prep ----------------
__global__ void box_prep(const float* __restrict__ rois1, const float* __restrict__ rois2) {
    int i = blockIdx.x * blockDim.x + threadIdx.x;
    if (i >= N_) return;
    {
        float xmin = rois1[i*4+0], ymin = rois1[i*4+1], xmax = rois1[i*4+2], ymax = rois1[i*4+3];
        float w = xmax - xmin + 1.0f, h = ymax - ymin + 1.0f;
        g_boxA[i*4+0] = 0.5f*(xmin+xmax); g_boxA[i*4+1] = 0.5f*(ymin+ymax);
        g_boxA[i*4+2] = 1.0f/w;           g_boxA[i*4+3] = 1.0f/h;
        float lw = logf(w), lh = logf(h);
#pragma unroll
        for (int f = 0; f < 8; f++) {
            float s, c;
            sincosf(lw * c_cf[f], &s, &c);
            g_trigA[i*32 + f] = s;      g_trigA[i*32 + 8 + f] = c;
            sincosf(lh * c_cf[f], &s, &c);
            g_trigA[i*32 + 16 + f] = s; g_trigA[i*32 + 24 + f] = c;
        }
    }
    {
        float xmin = rois2[i*4+0], ymin = rois2[i*4+1], xmax = rois2[i*4+2], ymax = rois2[i*4+3];
        float w = xmax - xmin + 1.0f, h = ymax - ymin + 1.0f;
        g_boxB[i*4+0] = 0.5f*(xmin+xmax); g_boxB[i*4+1] = 0.5f*(ymin+ymax);
        g_boxB[i*4+2] = 1.0f/w;           g_boxB[i*4+3] = 1.0f/h;
        float lw = logf(w), lh = logf(h);
#pragma unroll
        for (int f = 0; f < 8; f++) {
            float s, c;
            sincosf(lw * c_cf[f], &s, &c);
            g_trigBt[f*M_ + i] = s;        g_trigBt[(8+f)*M_ + i] = c;
            sincosf(lh * c_cf[f], &s, &c);
            g_trigBt[(16+f)*M_ + i] = s;   g_trigBt[(24+f)*M_ + i] = c;
        }
    }
}

// ---------------- fp32 -> bf16 hi/lo (row-major tensors) ----------------
__global__ __launch_bounds__(256) void conv_a(const float* __restrict__ roi,
                                              const float* __restrict__ ref,
                                              const float* __restrict__ wv) {
    const int z = blockIdx.y;
    const float4* src = (const float4*)(z == 0 ? roi : z == 1 ? ref : wv);
    uint2* dh = (uint2*)(z == 0 ? g_roiH : z == 1 ? g_refH : g_wvH);
    uint2* dl = (uint2*)(z == 0 ? g_roiL : z == 1 ? g_refL : g_wvL);
    int i = blockIdx.x * 256 + threadIdx.x;
    float4 x = src[i];
    uint32_t h01 = cvt2bf(x.x, x.y), h23 = cvt2bf(x.z, x.w);
    float l0 = x.x - bflo(h01), l1 = x.y - bfhi(h01);
    float l2 = x.z - bflo(h23), l3 = x.w - bfhi(h23);
    dh[i] = make_uint2(h01, h23);
    dl[i] = make_uint2(cvt2bf(l0, l1), cvt2bf(l2, l3));
}

// ---------------- Wq/Wk transpose + bf16 hi/lo: W[k][j] -> Wt[j][k] ----------------
__global__ __launch_bounds__(256) void conv_w(const float* __restrict__ Wq,
                                              const float* __restrict__ Wk) {
    __shared__ float ts[64][65];
    const int z = blockIdx.z;
    const float* W = z ? Wk : Wq;
    uint2* dh = (uint2*)(z ? g_wktH : g_wqtH);
    uint2* dl = (uint2*)(z ? g_wktL : g_wqtL);
    const int j0 = blockIdx.x * 64, k0 = blockIdx.y * 64;
    const int t = threadIdx.x;
#pragma unroll
    for (int it = 0; it < 4; it++) {
        int lin = it * 256 + t;
        int k = lin >> 4, j4 = (lin & 15) << 2;
        float4 v = *(const float4*)&W[(size_t)(k0 + k) * D_ + j0 + j4];
        ts[j4 + 0][k] = v.x; ts[j4 + 1][k] = v.y; ts[j4 + 2][k] = v.z; ts[j4 + 3][k] = v.w;
    }
    __syncthreads();
#pragma unroll
    for (int it = 0; it < 4; it++) {
        int lin = it * 256 + t;
        int j = lin >> 4, k4 = (lin & 15) << 2;
        float a = ts[j][k4 + 0], b = ts[j][k4 + 1], c = ts[j][k4 + 2], d = ts[j][k4 + 3];
        uint32_t h01 = cvt2bf(a, b), h23 = cvt2bf(c, d);
        float l0 = a - bflo(h01), l1 = b - bfhi(h01);
        float l2 = c - bflo(h23), l3 = d - bfhi(h23);
        size_t idx = ((size_t)(j0 + j) * D_ + k0 + k4) >> 2;
        dh[idx] = make_uint2(h01, h23);
        dl[idx] = make_uint2(cvt2bf(l0, l1), cvt2bf(l2, l3));
    }
}

// ---------------- tensor-core GEMM: 128m x 64n tiles, 2 blocks/SM (round-11) ----------------
#define OFF_AH 0
#define OFF_AL 16384
#define OFF_BH 32768
#define OFF_BL 40960
#define STAGE_BYTES 49152
#define TC_SMEM (2 * STAGE_BYTES)   // 98304

__global__ __launch_bounds__(256, 2) void tc_gemm(const float* __restrict__ bq,
                                                  const float* __restrict__ bk) {
    extern __shared__ char smem[];
    const uint32_t sb = smem_to_u32(smem);
    const int t = threadIdx.x;
    const int wid = t >> 5, lane = t & 31;
    const int j0 = blockIdx.x * 64, i0 = blockIdx.y * 128;
    const int mat = blockIdx.z;

    const uint16_t* Ah;
    const uint16_t* Al;
    const uint16_t* Bh;
    const uint16_t* Bl;
    if (mat == 0)      { Ah = g_roiH; Al = g_roiL; Bh = g_wqtH; Bl = g_wqtL; }
    else if (mat == 1) { Ah = g_refH; Al = g_refL; Bh = g_wktH; Bl = g_wktL; }
    else               { Ah = g_refH; Al = g_refL; Bh = g_wvH;  Bl = g_wvL; }

    const int wm = wid & 3, wn = wid >> 2;
    const int lr = lane & 7, lq = lane >> 3;

    float d[2][4][4];
#pragma unroll
    for (int a = 0; a < 2; a++)
#pragma unroll
        for (int b = 0; b < 4; b++)
#pragma unroll
            for (int c = 0; c < 4; c++) d[a][b][c] = 0.0f;

    const uint32_t a_off0 = (uint32_t)((wm*32 + (lq & 1)*8 + lr) * 128 + (lq >> 1) * 16);
    const uint32_t b_off0 = (uint32_t)((wn*32 + lr) * 128 + (lq & 1) * 16);

    auto loadChunk = [&](int ch, int stage) {
        const uint32_t sbase = sb + stage * STAGE_BYTES;
        {
            int row = t >> 1;
#pragma unroll
            for (int uu = 0; uu < 4; uu++) {
                int u = (t & 1) * 4 + uu;
                uint32_t so = SWZ((uint32_t)(row * 128 + u * 16));
                cp16(sbase + OFF_AH + so, Ah + ((size_t)(i0 + row) * 1024 + ch * 64 + u * 8));
                cp16(sbase + OFF_AL + so, Al + ((size_t)(i0 + row) * 1024 + ch * 64 + u * 8));
            }
        }
        {
            int row = t >> 2;
#pragma unroll
            for (int uu = 0; uu < 2; uu++) {
                int u = (t & 3) * 2 + uu;
                uint32_t so = SWZ((uint32_t)(row * 128 + u * 16));
                cp16(sbase + OFF_BH + so, Bh + ((size_t)(j0 + row) * 1024 + ch * 64 + u * 8));
                cp16(sbase + OFF_BL + so, Bl + ((size_t)(j0 + row) * 1024 + ch * 64 + u * 8));
            }
        }
    };

    loadChunk(0, 0);
    CP_COMMIT();

    for (int ch = 0; ch < 16; ch++) {
        if (ch + 1 < 16) {
            loadChunk(ch + 1, (ch + 1) & 1);
            CP_COMMIT();
            asm volatile("cp.async.wait_group 1;" ::: "memory");
        } else {
            asm volatile("cp.async.wait_group 0;" ::: "memory");
        }
        __syncthreads();

        const uint32_t st = sb + (ch & 1) * STAGE_BYTES;
#pragma unroll
        for (int ks = 0; ks < 4; ks++) {
            const uint32_t kb = (uint32_t)(ks * 32);
            uint32_t ah[2][4], al[2][4], bh[4][2], bl[4][2];
#pragma unroll
            for (int ma = 0; ma < 2; ma++) {
                uint32_t off = SWZ(a_off0 + (uint32_t)(ma * 16 * 128) + kb);
                ldsm_x4(ah[ma], st + OFF_AH + off);
                ldsm_x4(al[ma], st + OFF_AL + off);
            }
#pragma unroll
            for (int na = 0; na < 4; na++) {
                uint32_t off = SWZ(b_off0 + (uint32_t)(na * 8 * 128) + kb);
                ldsm_x2(bh[na], st + OFF_BH + off);
                ldsm_x2(bl[na], st + OFF_BL + off);
            }
#pragma unroll
            for (int ma = 0; ma < 2; ma++)
#pragma unroll
                for (int na = 0; na < 4; na++)
                    mma16816(d[ma][na], ah[ma], bh[na]);
#pragma unroll
            for (int ma = 0; ma < 2; ma++)
#pragma unroll
                for (int na = 0; na < 4; na++)
                    mma16816(d[ma][na], ah[ma], bl[na]);
#pragma unroll
            for (int ma = 0; ma < 2; ma++)
#pragma unroll
                for (int na = 0; na < 4; na++)
                    mma16816(d[ma][na], al[ma], bh[na]);
        }
        __syncthreads();
    }

    // stage D in smem: sd[128 i][68] cols j
    float* sd = (float*)smem;
    const int gid = lane >> 2, tig = lane & 3;
#pragma unroll
    for (int ma = 0; ma < 2; ma++)
#pragma unroll
        for (int na = 0; na < 4; na++) {
            int row = wm * 32 + ma * 16 + gid;
            int col = wn * 32 + na * 8 + 2 * tig;
            sd[row * 68 + col]           = d[ma][na][0];
            sd[row * 68 + col + 1]       = d[ma][na][1];
            sd[(row + 8) * 68 + col]     = d[ma][na][2];
            sd[(row + 8) * 68 + col + 1] = d[ma][na][3];
        }
    __syncthreads();

    if (mat != 2) {
        const float* bias = (mat == 0) ? bq : bk;
        uint16_t* dH = (mat == 0) ? g_qbH : g_kbH;
        uint16_t* dL = (mat == 0) ? g_qbL : g_kbL;
        int i = t >> 1, jh = (t & 1) * 32;
#pragma unroll
        for (int jj = 0; jj < 32; jj += 4) {
            float4 v = *(const float4*)&sd[i * 68 + jh + jj];
            float4 bb = *(const float4*)&bias[j0 + jh + jj];
            v.x += bb.x; v.y += bb.y; v.z += bb.z; v.w += bb.w;
            uint32_t h01 = cvt2bf(v.x, v.y), h23 = cvt2bf(v.z, v.w);
            float l0 = v.x - bflo(h01), l1 = v.y - bfhi(h01);
            float l2 = v.z - bflo(h23), l3 = v.w - bfhi(h23);
            size_t off = (size_t)(i0 + i) * 1024 + j0 + jh + jj;
            *(uint2*)&dH[off] = make_uint2(h01, h23);
            *(uint2*)&dL[off] = make_uint2(cvt2bf(l0, l1), cvt2bf(l2, l3));
        }
    } else {
        int j = t >> 2, ih = (t & 3) * 32;
#pragma unroll
        for (int mm = 0; mm < 32; mm += 4) {
            float v0 = sd[(ih + mm + 0) * 68 + j];
            float v1 = sd[(ih + mm + 1) * 68 + j];
            float v2 = sd[(ih + mm + 2) * 68 + j];
            float v3 = sd[(ih + mm + 3) * 68 + j];
            uint32_t h01 = cvt2bf(v0, v1), h23 = cvt2bf(v2, v3);
            float l0 = v0 - bflo(h01), l1 = v1 - bfhi(h01);
            float l2 = v2 - bflo(h23), l3 = v3 - bfhi(h23);
            size_t off = (size_t)(j0 + j) * 1024 + i0 + ih + mm;
            *(uint2*)&g_vtH[off] = make_uint2(h01, h23);
            *(uint2*)&g_vtL[off] = make_uint2(cvt2bf(l0, l1), cvt2bf(l2, l3));
        }
    }
}

// ---------------- position-weight kernel (round-11, unchanged) ----------------
__global__ __launch_bounds__(256, 2) void posw_kernel(const float* __restrict__ Wg,
                                                      const float* __restrict__ bg) {
    __shared__ float wgt[64][16];
    __shared__ float bgs[G_];
    const int t = threadIdx.x;
#pragma unroll
    for (int i = t; i < 1024; i += 256) {
        int g = i >> 6, e = i & 63;
        wgt[e][g] = Wg[i];
    }
    if (t < G_) bgs[t] = bg[t];
    __syncthreads();

    const int n = blockIdx.y;
    const int m0 = blockIdx.x * 512 + t;
    const int m1 = m0 + 256;

    u64 acc0[8], acc1[8];
#pragma unroll
    for (int gp = 0; gp < 8; gp++) {
        u64 b2 = pack2(bgs[2*gp], bgs[2*gp+1]);
        acc0[gp] = b2;
        acc1[gp] = b2;
    }

    auto upd = [&](int e, float v0, float v1) {
        const ulonglong2* wr = (const ulonglong2*)&wgt[e][0];
        ulonglong2 wa = wr[0], wb = wr[1];
        u64 d0 = dup2(v0), d1 = dup2(v1);
        fma2(acc0[0], d0, wa.x); fma2(acc1[0], d1, wa.x);
        fma2(acc0[1], d0, wa.y); fma2(acc1[1], d1, wa.y);
        fma2(acc0[2], d0, wb.x); fma2(acc1[2], d1, wb.x);
        fma2(acc0[3], d0, wb.y); fma2(acc1[3], d1, wb.y);
        ulonglong2 wc = wr[2], wd = wr[3];
        fma2(acc0[4], d0, wc.x); fma2(acc1[4], d1, wc.x);
        fma2(acc0[5], d0, wc.y); fma2(acc1[5], d1, wc.y);
        fma2(acc0[6], d0, wd.x); fma2(acc1[6], d1, wd.x);
        fma2(acc0[7], d0, wd.y); fma2(acc1[7], d1, wd.y);
    };

    const float4 bn = *(const float4*)&g_boxA[n * 4];
    const float4 bm0 = *(const float4*)&g_boxB[m0 * 4];
    const float4 bm1 = *(const float4*)&g_boxB[m1 * 4];

    {
        float px0 = __logf(fabsf(bn.x - bm0.x) * bn.z + 1e-3f);
        float px1 = __logf(fabsf(bn.x - bm1.x) * bn.z + 1e-3f);
#pragma unroll
        for (int f = 0; f < 8; f++) {
            float s0, c0, s1, c1;
            __sincosf(px0 * c_cf[f], &s0, &c0);
            __sincosf(px1 * c_cf[f], &s1, &c1);
            upd(f, s0, s1);
            upd(8 + f, c0, c1);
        }
        float py0 = __logf(fabsf(bn.y - bm0.y) * bn.w + 1e-3f);
        float py1 = __logf(fabsf(bn.y - bm1.y) * bn.w + 1e-3f);
#pragma unroll
        for (int f = 0; f < 8; f++) {
            float s0, c0, s1, c1;
            __sincosf(py0 * c_cf[f], &s0, &c0);
            __sincosf(py1 * c_cf[f], &s1, &c1);
            upd(16 + f, s0, s1);
            upd(24 + f, c0, c1);
        }
    }

#pragma unroll
    for (int f = 0; f < 8; f++) {
        float snf = g_trigA[n*32 + f], cnf = g_trigA[n*32 + 8 + f];
        float sm0 = g_trigBt[f*M_ + m0], cm0 = g_trigBt[(8+f)*M_ + m0];
        float sm1 = g_trigBt[f*M_ + m1], cm1 = g_trigBt[(8+f)*M_ + m1];
        upd(32 + f, snf*cm0 - cnf*sm0, snf*cm1 - cnf*sm1);
        upd(40 + f, fmaf(cnf, cm0, snf*sm0), fmaf(cnf, cm1, snf*sm1));
    }
#pragma unroll
    for (int f = 0; f < 8; f++) {
        float snf = g_trigA[n*32 + 16 + f], cnf = g_trigA[n*32 + 24 + f];
        float sm0 = g_trigBt[(16+f)*M_ + m0], cm0 = g_trigBt[(24+f)*M_ + m0];
        float sm1 = g_trigBt[(16+f)*M_ + m1], cm1 = g_trigBt[(24+f)*M_ + m1];
        upd(48 + f, snf*cm0 - cnf*sm0, snf*cm1 - cnf*sm1);
        upd(56 + f, fmaf(cnf, cm0, snf*sm0), fmaf(cnf, cm1, snf*sm1));
    }

    const size_t base = (size_t)n * G_ * M_;
#pragma unroll
    for (int gp = 0; gp < 8; gp++) {
        float x0, y0, x1, y1;
        unpack2(acc0[gp], x0, y0);
        unpack2(acc1[gp], x1, y1);
        g_w[base + (size_t)(2*gp)   * M_ + m0] = fmaxf(x0, 0.0f) + 1e-6f;
        g_w[base + (size_t)(2*gp+1) * M_ + m0] = fmaxf(y0, 0.0f) + 1e-6f;
        g_w[base + (size_t)(2*gp)   * M_ + m1] = fmaxf(x1, 0.0f) + 1e-6f;
        g_w[base + (size_t)(2*gp+1) * M_ + m1] = fmaxf(y1, 0.0f) + 1e-6f;
    }
}

// ---------------- flash on tensor cores (round-11, unchanged) ----------------
#define FQ_H 0
#define FQ_L 16384
#define FSTG 32768
#define FS_KH 0
#define FS_KL 8192
#define FS_VH 16384
#define FS_VL 24576
#define FSTG_BYTES 32768
#define FLASH_SMEM (32768 + 2 * 32768)   // 98304

__global__ __launch_bounds__(256, 2) void flash_kernel() {
    extern __shared__ char smem[];
    const uint32_t sb = smem_to_u32(smem);
    const int t = threadIdx.x;
    const int wid = t >> 5, lane = t & 31;
    const int lr = lane & 7, lq = lane >> 3;
    const int gid = lane >> 2, tig = lane & 3;
    const int g = blockIdx.y;
    const int n0 = blockIdx.x * 128;
    const int z = blockIdx.z;

    const uint32_t a_off0 = (uint32_t)((wid*16 + (lq & 1)*8 + lr) * 128 + (lq >> 1) * 16);
    const uint32_t b_off0 = (uint32_t)(lr * 128 + (lq & 1) * 16);

    {
        int row = t >> 1;
#pragma unroll
        for (int uu = 0; uu < 4; uu++) {
            int u = (t & 1) * 4 + uu;
            uint32_t so = SWZ((uint32_t)(row * 128 + u * 16));
            cp16(sb + FQ_H + so, g_qbH + ((size_t)(n0 + row) * 1024 + g * 64 + u * 8));
            cp16(sb + FQ_L + so, g_qbL + ((size_t)(n0 + row) * 1024 + g * 64 + u * 8));
        }
    }
    auto loadStage = [&](int it, int stg) {
        const uint32_t sbase = sb + FSTG + stg * FSTG_BYTES;
        const int m0 = z * 512 + it * 64;
        int row = t >> 2;
#pragma unroll
        for (int uu = 0; uu < 2; uu++) {
            int u = (t & 3) * 2 + uu;
            uint32_t so = SWZ((uint32_t)(row * 128 + u * 16));
            cp16(sbase + FS_KH + so, g_kbH + ((size_t)(m0 + row) * 1024 + g * 64 + u * 8));
            cp16(sbase + FS_KL + so, g_kbL + ((size_t)(m0 + row) * 1024 + g * 64 + u * 8));
            cp16(sbase + FS_VH + so, g_vtH + ((size_t)(g * 64 + row) * 1024 + m0 + u * 8));
            cp16(sbase + FS_VL + so, g_vtL + ((size_t)(g * 64 + row) * 1024 + m0 + u * 8));
        }
    };

    loadStage(0, 0);
    CP_COMMIT();

    float o_[8][4];
#pragma unroll
    for (int a = 0; a < 8; a++)
#pragma unroll
        for (int b = 0; b < 4; b++) o_[a][b] = 0.0f;
    float lr0 = 0.0f, lr1 = 0.0f;

    for (int it = 0; it < 8; it++) {
        if (it + 1 < 8) {
            loadStage(it + 1, (it + 1) & 1);
            CP_COMMIT();
            asm volatile("cp.async.wait_group 1;" ::: "memory");
        } else {
            asm volatile("cp.async.wait_group 0;" ::: "memory");
        }
        __syncthreads();

        const uint32_t st = sb + FSTG + (it & 1) * FSTG_BYTES;
        const int m0 = z * 512 + it * 64;

        float s[8][4];
#pragma unroll
        for (int a = 0; a < 8; a++)
#pragma unroll
            for (int b = 0; b < 4; b++) s[a][b] = 0.0f;

#pragma unroll
        for (int dc = 0; dc < 4; dc++) {
            uint32_t aoff = SWZ(a_off0 + (uint32_t)(dc * 32));
            uint32_t aqh[4], aql[4];
            ldsm_x4(aqh, sb + FQ_H + aoff);
            ldsm_x4(aql, sb + FQ_L + aoff);
#pragma unroll
            for (int mt = 0; mt < 8; mt++) {
                uint32_t boff = SWZ(b_off0 + (uint32_t)(mt * 8 * 128 + dc * 32));
                uint32_t bkh[2], bkl[2];
                ldsm_x2(bkh, st + FS_KH + boff);
                ldsm_x2(bkl, st + FS_KL + boff);
                mma16816(s[mt], aqh, bkh);
                mma16816(s[mt], aqh, bkl);
                mma16816(s[mt], aql, bkh);
            }
        }

        uint32_t paH[4][4], paL[4][4];
        const size_t wbase0 = ((size_t)(n0 + wid * 16 + gid) * G_ + g) * M_;
        const size_t wbase1 = wbase0 + (size_t)8 * G_ * M_;
#pragma unroll
        for (int mt = 0; mt < 8; mt++) {
            int mcol = m0 + mt * 8 + 2 * tig;
            float2 w0 = *(const float2*)&g_w[wbase0 + mcol];
            float2 w1 = *(const float2*)&g_w[wbase1 + mcol];
            float p0 = w0.x * fast_exp(s[mt][0] * 0.125f);
            float p1 = w0.y * fast_exp(s[mt][1] * 0.125f);
            float p2 = w1.x * fast_exp(s[mt][2] * 0.125f);
            float p3 = w1.y * fast_exp(s[mt][3] * 0.125f);
            lr0 += p0 + p1;
            lr1 += p2 + p3;
            uint32_t h01 = cvt2bf(p0, p1), h23 = cvt2bf(p2, p3);
            float l0 = p0 - bflo(h01), l1 = p1 - bfhi(h01);
            float l2 = p2 - bflo(h23), l3 = p3 - bfhi(h23);
            int kc = mt >> 1, hf = (mt & 1) * 2;
            paH[kc][hf + 0] = h01;
            paH[kc][hf + 1] = h23;
            paL[kc][hf + 0] = cvt2bf(l0, l1);
            paL[kc][hf + 1] = cvt2bf(l2, l3);
        }

#pragma unroll
        for (int kc = 0; kc < 4; kc++) {
#pragma unroll
            for (int ot = 0; ot < 8; ot++) {
                uint32_t boff = SWZ(b_off0 + (uint32_t)(ot * 8 * 128 + kc * 32));
                uint32_t bvh[2], bvl[2];
                ldsm_x2(bvh, st + FS_VH + boff);
                ldsm_x2(bvl, st + FS_VL + boff);
                mma16816(o_[ot], paH[kc], bvh);
                mma16816(o_[ot], paH[kc], bvl);
                mma16816(o_[ot], paL[kc], bvh);
            }
        }
        __syncthreads();
    }

    lr0 += __shfl_xor_sync(0xffffffffu, lr0, 1);
    lr0 += __shfl_xor_sync(0xffffffffu, lr0, 2);
    lr1 += __shfl_xor_sync(0xffffffffu, lr1, 1);
    lr1 += __shfl_xor_sync(0xffffffffu, lr1, 2);

    const int r0 = n0 + wid * 16 + gid;
    if (tig == 0) {
        g_pl[z][(size_t)r0 * G_ + g] = lr0;
        g_pl[z][(size_t)(r0 + 8) * G_ + g] = lr1;
    }
#pragma unroll
    for (int ot = 0; ot < 8; ot++) {
        int col = g * 64 + ot * 8 + 2 * tig;
        *(float2*)&g_pacc[z][(size_t)r0 * D_ + col] = make_float2(o_[ot][0], o_[ot][1]);
        *(float2*)&g_pacc[z][(size_t)(r0 + 8) * D_ + col] = make_float2(o_[ot][2], o_[ot][3]);
    }
}

// ---------------- combine partials ----------------
__global__ __launch_bounds__(256) void reduce_kernel(const float* __restrict__ bv,
                                                     float* __restrict__ out) {
    int idx = blockIdx.x * 256 + threadIdx.x;
    int n = idx >> 8;
    int col = (idx & 255) << 2;
    int g = col >> 6;
    float l = 0.0f;
    float4 a = make_float4(0.f, 0.f, 0.f, 0.f);
#pragma unroll
    for (int zz = 0; zz < SPLITS; zz++) {
        l += g_pl[zz][(size_t)n * G_ + g];
        float4 p = *(const float4*)&g_pacc[zz][(size_t)n * D_ + col];
        a.x += p.x; a.y += p.y; a.z += p.z; a.w += p.w;
    }
    float inv = 1.0f / l;
    float4 b4 = *(const float4*)&bv[col];
    float4 o;
    o.x = fmaf(a.x, inv, b4.x);
    o.y = fmaf(a.y, inv, b4.y);
    o.z = fmaf(a.z, inv, b4.z);
    o.w = fmaf(a.w, inv, b4.w);
    *(float4*)&out[(size_t)n * D_ + col] = o;
}

// ---------------- host launcher: two independent chains on two streams ----------------
extern "C" void kernel_launch(void* const* d_in, const int* in_sizes, int n_in,
                              void* d_out, int out_size) {
    const float* roi   = (const float*)d_in[0];
    const float* ref   = (const float*)d_in[1];
    const float* rois1 = (const float*)d_in[2];
    const float* rois2 = (const float*)d_in[3];
    const float* Wq    = (const float*)d_in[4];
    const float* bq    = (const float*)d_in[5];
    const float* Wk    = (const float*)d_in[6];
    const float* bk    = (const float*)d_in[7];
    const float* Wg    = (const float*)d_in[8];
    const float* bg    = (const float*)d_in[9];
    const float* Wv    = (const float*)d_in[10];
    const float* bv    = (const float*)d_in[11];
    float* out = (float*)d_out;

    static cudaStream_t s2 = nullptr;
    static cudaEvent_t evFork = nullptr, evJoin = nullptr;
    static bool init_done = false;
    if (!init_done) {
        cudaFuncSetAttribute(flash_kernel, cudaFuncAttributeMaxDynamicSharedMemorySize, FLASH_SMEM);
        cudaFuncSetAttribute(tc_gemm, cudaFuncAttributeMaxDynamicSharedMemorySize, TC_SMEM);
        cudaStreamCreateWithFlags(&s2, cudaStreamNonBlocking);
        cudaEventCreateWithFlags(&evFork, cudaEventDisableTiming);
        cudaEventCreateWithFlags(&evJoin, cudaEventDisableTiming);
        init_done = true;
    }

    // fork: side chain (box_prep -> posw) on s2
    cudaEventRecord(evFork, 0);
    cudaStreamWaitEvent(s2, evFork, 0);
    box_prep<<<4, 256, 0, s2>>>(rois1, rois2);
    posw_kernel<<<dim3(2, 1024), 256, 0, s2>>>(Wg, bg);
    cudaEventRecord(evJoin, s2);

    // main chain: conv -> tc_gemm on default stream
    conv_a<<<dim3(1024, 3), 256>>>(roi, ref, Wv);
    conv_w<<<dim3(16, 16, 2), 256>>>(Wq, Wk);
    tc_gemm<<<dim3(16, 8, 3), 256, TC_SMEM>>>(bq, bk);

    // join, then flash + reduce
    cudaStreamWaitEvent(0, evJoin, 0);
    flash_kernel<<<dim3(8, 16, 2), 256, FLASH_SMEM>>>();
    reduce_kernel<<<1024, 256>>>(bv, out);
}

// round 16
// speedup vs baseline: 1.3150x; 1.0372x over previous
#include <cuda_runtime.h>
#include <cuda_bf16.h>
#include <math.h>
#include <stdint.h>

#define N_ 1024
#define M_ 1024
#define D_ 1024
#define G_ 16
#define DG_ 64
#define SPLITS 2

typedef unsigned long long u64;

// ---------------- scratch ----------------
__device__ float g_w[(size_t)N_ * G_ * M_];      // (N, G, M)
__device__ float g_boxA[N_ * 4];
__device__ float g_boxB[M_ * 4];
__device__ float g_trigA[N_ * 32];
__device__ float g_trigBt[32 * M_];
__device__ float g_pacc[SPLITS][(size_t)N_ * D_];
__device__ float g_pl[SPLITS][(size_t)N_ * G_];

// bf16 hi/lo operand buffers
#define MEG (1024 * 1024)
__device__ __align__(16) uint16_t g_roiH[MEG], g_roiL[MEG];
__device__ __align__(16) uint16_t g_refH[MEG], g_refL[MEG];
__device__ __align__(16) uint16_t g_wvH[MEG],  g_wvL[MEG];
__device__ __align__(16) uint16_t g_wqtH[MEG], g_wqtL[MEG];   // Wq^T [j][k]
__device__ __align__(16) uint16_t g_wktH[MEG], g_wktL[MEG];   // Wk^T [j][k]
// GEMM outputs (bf16), MMA-ready layouts for flash
__device__ __align__(16) uint16_t g_qbH[MEG];                 // q [n][d] (hi only)
__device__ __align__(16) uint16_t g_kbH[MEG], g_kbL[MEG];     // k [m][d]
__device__ __align__(16) uint16_t g_vtH[MEG], g_vtL[MEG];     // v^T [o][m]

// ---------------- f32x2 helpers ----------------
__device__ __forceinline__ void fma2(u64& d, u64 a, u64 b) {
    asm("fma.rn.f32x2 %0, %1, %2, %0;" : "+l"(d) : "l"(a), "l"(b));
}
__device__ __forceinline__ u64 pack2(float x, float y) {
    u64 r;
    asm("mov.b64 %0, {%1, %2};" : "=l"(r) : "f"(x), "f"(y));
    return r;
}
__device__ __forceinline__ void unpack2(u64 p, float& x, float& y) {
    asm("mov.b64 {%0, %1}, %2;" : "=f"(x), "=f"(y) : "l"(p));
}
__device__ __forceinline__ u64 dup2(float x) { return pack2(x, x); }

__device__ __forceinline__ float fast_exp(float x) {
    float t = x * 1.4426950408889634f;
    t = fminf(fmaxf(t, -120.0f), 120.0f);
    float fi = floorf(t);
    float f = t - fi;
    float p = 1.5403530393e-4f;
    p = fmaf(p, f, 1.3333558146e-3f);
    p = fmaf(p, f, 9.6181291076e-3f);
    p = fmaf(p, f, 5.5504108664e-2f);
    p = fmaf(p, f, 2.4022650696e-1f);
    p = fmaf(p, f, 6.9314718056e-1f);
    p = fmaf(p, f, 1.0f);
    return p * __int_as_float(((int)fi + 127) << 23);
}

__constant__ float c_cf[8] = {100.0f, 42.169650f, 17.782794f, 7.4989421f,
                              3.1622776f, 1.3335214f, 0.56234133f, 0.23713737f};

// ---------------- mma / bf16 helpers (baseline PTX) ----------------
__device__ __forceinline__ uint32_t smem_to_u32(const void* p) {
    uint32_t a;
    asm("{ .reg .u64 t; cvta.to.shared.u64 t, %1; cvt.u32.u64 %0, t; }" : "=r"(a) : "l"(p));
    return a;
}
__device__ __forceinline__ void mma16816(float* d, const uint32_t* a, const uint32_t* b) {
    asm volatile(
        "mma.sync.aligned.m16n8k16.row.col.f32.bf16.bf16.f32 "
        "{%0,%1,%2,%3}, {%4,%5,%6,%7}, {%8,%9}, {%0,%1,%2,%3};"
        : "+f"(d[0]), "+f"(d[1]), "+f"(d[2]), "+f"(d[3])
        : "r"(a[0]), "r"(a[1]), "r"(a[2]), "r"(a[3]), "r"(b[0]), "r"(b[1]));
}
__device__ __forceinline__ void ldsm_x4(uint32_t* r, uint32_t addr) {
    asm volatile("ldmatrix.sync.aligned.m8n8.x4.shared.b16 {%0,%1,%2,%3}, [%4];"
                 : "=r"(r[0]), "=r"(r[1]), "=r"(r[2]), "=r"(r[3]) : "r"(addr));
}
__device__ __forceinline__ void ldsm_x2(uint32_t* r, uint32_t addr) {
    asm volatile("ldmatrix.sync.aligned.m8n8.x2.shared.b16 {%0,%1}, [%2];"
                 : "=r"(r[0]), "=r"(r[1]) : "r"(addr));
}
__device__ __forceinline__ void cp16(uint32_t saddr, const void* gptr) {
    asm volatile("cp.async.cg.shared.global [%0], [%1], 16;" :: "r"(saddr), "l"(gptr));
}
#define CP_COMMIT() asm volatile("cp.async.commit_group;" ::: "memory")
#define SWZ(bo) ((bo) ^ (((bo) >> 3) & 0x70))

// pack (lo, hi) floats -> bf16x2 register (lo in bits [0:16))
__device__ __forceinline__ uint32_t cvt2bf(float lo, float hi) {
    uint32_t r;
    asm("cvt.rn.satfinite.bf16x2.f32 %0, %1, %2;" : "=r"(r) : "f"(hi), "f"(lo));
    return r;
}
__device__ __forceinline__ float bflo(uint32_t p) { return __uint_as_float(p << 16); }
__device__ __forceinline__ float bfhi(uint32_t p) { return __uint_as_float(p & 0xFFFF0000u); }

// ---------------- box prep ----------------
__global__ void box_prep(const float* __restrict__ rois1, const float* __restrict__ rois2) {
    int i = blockIdx.x * blockDim.x + threadIdx.x;
    if (i >= N_) return;
    {
        float xmin = rois1[i*4+0], ymin = rois1[i*4+1], xmax = rois1[i*4+2], ymax = rois1[i*4+3];
        float w = xmax - xmin + 1.0f, h = ymax - ymin + 1.0f;
        g_boxA[i*4+0] = 0.5f*(xmin+xmax); g_boxA[i*4+1] = 0.5f*(ymin+ymax);
        g_boxA[i*4+2] = 1.0f/w;           g_boxA[i*4+3] = 1.0f/h;
        float lw = logf(w), lh = logf(h);
#pragma unroll
        for (int f = 0; f < 8; f++) {
            float s, c;
            sincosf(lw * c_cf[f], &s, &c);
            g_trigA[i*32 + f] = s;      g_trigA[i*32 + 8 + f] = c;
            sincosf(lh * c_cf[f], &s, &c);
            g_trigA[i*32 + 16 + f] = s; g_trigA[i*32 + 24 + f] = c;
        }
    }
    {
        float xmin = rois2[i*4+0], ymin = rois2[i*4+1], xmax = rois2[i*4+2], ymax = rois2[i*4+3];
        float w = xmax - xmin + 1.0f, h = ymax - ymin + 1.0f;
        g_boxB[i*4+0] = 0.5f*(xmin+xmax); g_boxB[i*4+1] = 0.5f*(ymin+ymax);
        g_boxB[i*4+2] = 1.0f/w;           g_boxB[i*4+3] = 1.0f/h;
        float lw = logf(w), lh = logf(h);
#pragma unroll
        for (int f = 0; f < 8; f++) {
            float s, c;
            sincosf(lw * c_cf[f], &s, &c);
            g_trigBt[f*M_ + i] = s;        g_trigBt[(8+f)*M_ + i] = c;
            sincosf(lh * c_cf[f], &s, &c);
            g_trigBt[(16+f)*M_ + i] = s;   g_trigBt[(24+f)*M_ + i] = c;
        }
    }
}

// ---------------- fp32 -> bf16 hi/lo (row-major tensors) ----------------
__global__ __launch_bounds__(256) void conv_a(const float* __restrict__ roi,
                                              const float* __restrict__ ref,
                                              const float* __restrict__ wv) {
    const int z = blockIdx.y;
    const float4* src = (const float4*)(z == 0 ? roi : z == 1 ? ref : wv);
    uint2* dh = (uint2*)(z == 0 ? g_roiH : z == 1 ? g_refH : g_wvH);
    uint2* dl = (uint2*)(z == 0 ? g_roiL : z == 1 ? g_refL : g_wvL);
    int i = blockIdx.x * 256 + threadIdx.x;
    float4 x = src[i];
    uint32_t h01 = cvt2bf(x.x, x.y), h23 = cvt2bf(x.z, x.w);
    float l0 = x.x - bflo(h01), l1 = x.y - bfhi(h01);
    float l2 = x.z - bflo(h23), l3 = x.w - bfhi(h23);
    dh[i] = make_uint2(h01, h23);
    dl[i] = make_uint2(cvt2bf(l0, l1), cvt2bf(l2, l3));
}

// ---------------- Wq/Wk transpose + bf16 hi/lo: W[k][j] -> Wt[j][k] ----------------
__global__ __launch_bounds__(256) void conv_w(const float* __restrict__ Wq,
                                              const float* __restrict__ Wk) {
    __shared__ float ts[64][65];
    const int z = blockIdx.z;
    const float* W = z ? Wk : Wq;
    uint2* dh = (uint2*)(z ? g_wktH : g_wqtH);
    uint2* dl = (uint2*)(z ? g_wktL : g_wqtL);
    const int j0 = blockIdx.x * 64, k0 = blockIdx.y * 64;
    const int t = threadIdx.x;
#pragma unroll
    for (int it = 0; it < 4; it++) {
        int lin = it * 256 + t;
        int k = lin >> 4, j4 = (lin & 15) << 2;
        float4 v = *(const float4*)&W[(size_t)(k0 + k) * D_ + j0 + j4];
        ts[j4 + 0][k] = v.x; ts[j4 + 1][k] = v.y; ts[j4 + 2][k] = v.z; ts[j4 + 3][k] = v.w;
    }
    __syncthreads();
#pragma unroll
    for (int it = 0; it < 4; it++) {
        int lin = it * 256 + t;
        int j = lin >> 4, k4 = (lin & 15) << 2;
        float a = ts[j][k4 + 0], b = ts[j][k4 + 1], c = ts[j][k4 + 2], d = ts[j][k4 + 3];
        uint32_t h01 = cvt2bf(a, b), h23 = cvt2bf(c, d);
        float l0 = a - bflo(h01), l1 = b - bfhi(h01);
        float l2 = c - bflo(h23), l3 = d - bfhi(h23);
        size_t idx = ((size_t)(j0 + j) * D_ + k0 + k4) >> 2;
        dh[idx] = make_uint2(h01, h23);
        dl[idx] = make_uint2(cvt2bf(l0, l1), cvt2bf(l2, l3));
    }
}

// ---------------- tensor-core GEMM: 128m x 64n tiles, full 3-product ----------------
// mat 0: q (hi-only store), mat 1: k (hi/lo), mat 2: vt (hi/lo, transposed).
#define OFF_AH 0
#define OFF_AL 16384
#define OFF_BH 32768
#define OFF_BL 40960
#define STAGE_BYTES 49152
#define TC_SMEM (2 * STAGE_BYTES)   // 98304

__global__ __launch_bounds__(256, 2) void tc_gemm(const float* __restrict__ bq,
                                                  const float* __restrict__ bk) {
    extern __shared__ char smem[];
    const uint32_t sb = smem_to_u32(smem);
    const int t = threadIdx.x;
    const int wid = t >> 5, lane = t & 31;
    const int j0 = blockIdx.x * 64, i0 = blockIdx.y * 128;
    const int mat = blockIdx.z;

    const uint16_t* Ah;
    const uint16_t* Al;
    const uint16_t* Bh;
    const uint16_t* Bl;
    if (mat == 0)      { Ah = g_roiH; Al = g_roiL; Bh = g_wqtH; Bl = g_wqtL; }
    else if (mat == 1) { Ah = g_refH; Al = g_refL; Bh = g_wktH; Bl = g_wktL; }
    else               { Ah = g_refH; Al = g_refL; Bh = g_wvH;  Bl = g_wvL; }

    const int wm = wid & 3, wn = wid >> 2;
    const int lr = lane & 7, lq = lane >> 3;

    float d[2][4][4];
#pragma unroll
    for (int a = 0; a < 2; a++)
#pragma unroll
        for (int b = 0; b < 4; b++)
#pragma unroll
            for (int c = 0; c < 4; c++) d[a][b][c] = 0.0f;

    const uint32_t a_off0 = (uint32_t)((wm*32 + (lq & 1)*8 + lr) * 128 + (lq >> 1) * 16);
    const uint32_t b_off0 = (uint32_t)((wn*32 + lr) * 128 + (lq & 1) * 16);

    auto loadChunk = [&](int ch, int stage) {
        const uint32_t sbase = sb + stage * STAGE_BYTES;
        {
            int row = t >> 1;
#pragma unroll
            for (int uu = 0; uu < 4; uu++) {
                int u = (t & 1) * 4 + uu;
                uint32_t so = SWZ((uint32_t)(row * 128 + u * 16));
                cp16(sbase + OFF_AH + so, Ah + ((size_t)(i0 + row) * 1024 + ch * 64 + u * 8));
                cp16(sbase + OFF_AL + so, Al + ((size_t)(i0 + row) * 1024 + ch * 64 + u * 8));
            }
        }
        {
            int row = t >> 2;
#pragma unroll
            for (int uu = 0; uu < 2; uu++) {
                int u = (t & 3) * 2 + uu;
                uint32_t so = SWZ((uint32_t)(row * 128 + u * 16));
                cp16(sbase + OFF_BH + so, Bh + ((size_t)(j0 + row) * 1024 + ch * 64 + u * 8));
                cp16(sbase + OFF_BL + so, Bl + ((size_t)(j0 + row) * 1024 + ch * 64 + u * 8));
            }
        }
    };

    loadChunk(0, 0);
    CP_COMMIT();

    for (int ch = 0; ch < 16; ch++) {
        if (ch + 1 < 16) {
            loadChunk(ch + 1, (ch + 1) & 1);
            CP_COMMIT();
            asm volatile("cp.async.wait_group 1;" ::: "memory");
        } else {
            asm volatile("cp.async.wait_group 0;" ::: "memory");
        }
        __syncthreads();

        const uint32_t st = sb + (ch & 1) * STAGE_BYTES;
#pragma unroll
        for (int ks = 0; ks < 4; ks++) {
            const uint32_t kb = (uint32_t)(ks * 32);
            uint32_t ah[2][4], al[2][4], bh[4][2], bl[4][2];
#pragma unroll
            for (int ma = 0; ma < 2; ma++) {
                uint32_t off = SWZ(a_off0 + (uint32_t)(ma * 16 * 128) + kb);
                ldsm_x4(ah[ma], st + OFF_AH + off);
                ldsm_x4(al[ma], st + OFF_AL + off);
            }
#pragma unroll
            for (int na = 0; na < 4; na++) {
                uint32_t off = SWZ(b_off0 + (uint32_t)(na * 8 * 128) + kb);
                ldsm_x2(bh[na], st + OFF_BH + off);
                ldsm_x2(bl[na], st + OFF_BL + off);
            }
#pragma unroll
            for (int ma = 0; ma < 2; ma++)
#pragma unroll
                for (int na = 0; na < 4; na++)
                    mma16816(d[ma][na], ah[ma], bh[na]);
#pragma unroll
            for (int ma = 0; ma < 2; ma++)
#pragma unroll
                for (int na = 0; na < 4; na++)
                    mma16816(d[ma][na], ah[ma], bl[na]);
#pragma unroll
            for (int ma = 0; ma < 2; ma++)
#pragma unroll
                for (int na = 0; na < 4; na++)
                    mma16816(d[ma][na], al[ma], bh[na]);
        }
        __syncthreads();
    }

    // stage D in smem: sd[128 i][68] cols j
    float* sd = (float*)smem;
    const int gid = lane >> 2, tig = lane & 3;
#pragma unroll
    for (int ma = 0; ma < 2; ma++)
#pragma unroll
        for (int na = 0; na < 4; na++) {
            int row = wm * 32 + ma * 16 + gid;
            int col = wn * 32 + na * 8 + 2 * tig;
            sd[row * 68 + col]           = d[ma][na][0];
            sd[row * 68 + col + 1]       = d[ma][na][1];
            sd[(row + 8) * 68 + col]     = d[ma][na][2];
            sd[(row + 8) * 68 + col + 1] = d[ma][na][3];
        }
    __syncthreads();

    if (mat == 0) {
        // q: hi-only bf16 store with bias
        int i = t >> 1, jh = (t & 1) * 32;
#pragma unroll
        for (int jj = 0; jj < 32; jj += 4) {
            float4 v = *(const float4*)&sd[i * 68 + jh + jj];
            float4 bb = *(const float4*)&bq[j0 + jh + jj];
            v.x += bb.x; v.y += bb.y; v.z += bb.z; v.w += bb.w;
            uint32_t h01 = cvt2bf(v.x, v.y), h23 = cvt2bf(v.z, v.w);
            size_t off = (size_t)(i0 + i) * 1024 + j0 + jh + jj;
            *(uint2*)&g_qbH[off] = make_uint2(h01, h23);
        }
    } else if (mat == 1) {
        int i = t >> 1, jh = (t & 1) * 32;
#pragma unroll
        for (int jj = 0; jj < 32; jj += 4) {
            float4 v = *(const float4*)&sd[i * 68 + jh + jj];
            float4 bb = *(const float4*)&bk[j0 + jh + jj];
            v.x += bb.x; v.y += bb.y; v.z += bb.z; v.w += bb.w;
            uint32_t h01 = cvt2bf(v.x, v.y), h23 = cvt2bf(v.z, v.w);
            float l0 = v.x - bflo(h01), l1 = v.y - bfhi(h01);
            float l2 = v.z - bflo(h23), l3 = v.w - bfhi(h23);
            size_t off = (size_t)(i0 + i) * 1024 + j0 + jh + jj;
            *(uint2*)&g_kbH[off] = make_uint2(h01, h23);
            *(uint2*)&g_kbL[off] = make_uint2(cvt2bf(l0, l1), cvt2bf(l2, l3));
        }
    } else {
        int j = t >> 2, ih = (t & 3) * 32;
#pragma unroll
        for (int mm = 0; mm < 32; mm += 4) {
            float v0 = sd[(ih + mm + 0) * 68 + j];
            float v1 = sd[(ih + mm + 1) * 68 + j];
            float v2 = sd[(ih + mm + 2) * 68 + j];
            float v3 = sd[(ih + mm + 3) * 68 + j];
            uint32_t h01 = cvt2bf(v0, v1), h23 = cvt2bf(v2, v3);
            float l0 = v0 - bflo(h01), l1 = v1 - bfhi(h01);
            float l2 = v2 - bflo(h23), l3 = v3 - bfhi(h23);
            size_t off = (size_t)(j0 + j) * 1024 + i0 + ih + mm;
            *(uint2*)&g_vtH[off] = make_uint2(h01, h23);
            *(uint2*)&g_vtL[off] = make_uint2(cvt2bf(l0, l1), cvt2bf(l2, l3));
        }
    }
}

// ---------------- position-weight kernel (unchanged) ----------------
__global__ __launch_bounds__(256, 2) void posw_kernel(const float* __restrict__ Wg,
                                                      const float* __restrict__ bg) {
    __shared__ float wgt[64][16];
    __shared__ float bgs[G_];
    const int t = threadIdx.x;
#pragma unroll
    for (int i = t; i < 1024; i += 256) {
        int g = i >> 6, e = i & 63;
        wgt[e][g] = Wg[i];
    }
    if (t < G_) bgs[t] = bg[t];
    __syncthreads();

    const int n = blockIdx.y;
    const int m0 = blockIdx.x * 512 + t;
    const int m1 = m0 + 256;

    u64 acc0[8], acc1[8];
#pragma unroll
    for (int gp = 0; gp < 8; gp++) {
        u64 b2 = pack2(bgs[2*gp], bgs[2*gp+1]);
        acc0[gp] = b2;
        acc1[gp] = b2;
    }

    auto upd = [&](int e, float v0, float v1) {
        const ulonglong2* wr = (const ulonglong2*)&wgt[e][0];
        ulonglong2 wa = wr[0], wb = wr[1];
        u64 d0 = dup2(v0), d1 = dup2(v1);
        fma2(acc0[0], d0, wa.x); fma2(acc1[0], d1, wa.x);
        fma2(acc0[1], d0, wa.y); fma2(acc1[1], d1, wa.y);
        fma2(acc0[2], d0, wb.x); fma2(acc1[2], d1, wb.x);
        fma2(acc0[3], d0, wb.y); fma2(acc1[3], d1, wb.y);
        ulonglong2 wc = wr[2], wd = wr[3];
        fma2(acc0[4], d0, wc.x); fma2(acc1[4], d1, wc.x);
        fma2(acc0[5], d0, wc.y); fma2(acc1[5], d1, wc.y);
        fma2(acc0[6], d0, wd.x); fma2(acc1[6], d1, wd.x);
        fma2(acc0[7], d0, wd.y); fma2(acc1[7], d1, wd.y);
    };

    const float4 bn = *(const float4*)&g_boxA[n * 4];
    const float4 bm0 = *(const float4*)&g_boxB[m0 * 4];
    const float4 bm1 = *(const float4*)&g_boxB[m1 * 4];

    {
        float px0 = __logf(fabsf(bn.x - bm0.x) * bn.z + 1e-3f);
        float px1 = __logf(fabsf(bn.x - bm1.x) * bn.z + 1e-3f);
#pragma unroll
        for (int f = 0; f < 8; f++) {
            float s0, c0, s1, c1;
            __sincosf(px0 * c_cf[f], &s0, &c0);
            __sincosf(px1 * c_cf[f], &s1, &c1);
            upd(f, s0, s1);
            upd(8 + f, c0, c1);
        }
        float py0 = __logf(fabsf(bn.y - bm0.y) * bn.w + 1e-3f);
        float py1 = __logf(fabsf(bn.y - bm1.y) * bn.w + 1e-3f);
#pragma unroll
        for (int f = 0; f < 8; f++) {
            float s0, c0, s1, c1;
            __sincosf(py0 * c_cf[f], &s0, &c0);
            __sincosf(py1 * c_cf[f], &s1, &c1);
            upd(16 + f, s0, s1);
            upd(24 + f, c0, c1);
        }
    }

#pragma unroll
    for (int f = 0; f < 8; f++) {
        float snf = g_trigA[n*32 + f], cnf = g_trigA[n*32 + 8 + f];
        float sm0 = g_trigBt[f*M_ + m0], cm0 = g_trigBt[(8+f)*M_ + m0];
        float sm1 = g_trigBt[f*M_ + m1], cm1 = g_trigBt[(8+f)*M_ + m1];
        upd(32 + f, snf*cm0 - cnf*sm0, snf*cm1 - cnf*sm1);
        upd(40 + f, fmaf(cnf, cm0, snf*sm0), fmaf(cnf, cm1, snf*sm1));
    }
#pragma unroll
    for (int f = 0; f < 8; f++) {
        float snf = g_trigA[n*32 + 16 + f], cnf = g_trigA[n*32 + 24 + f];
        float sm0 = g_trigBt[(16+f)*M_ + m0], cm0 = g_trigBt[(24+f)*M_ + m0];
        float sm1 = g_trigBt[(16+f)*M_ + m1], cm1 = g_trigBt[(24+f)*M_ + m1];
        upd(48 + f, snf*cm0 - cnf*sm0, snf*cm1 - cnf*sm1);
        upd(56 + f, fmaf(cnf, cm0, snf*sm0), fmaf(cnf, cm1, snf*sm1));
    }

    const size_t base = (size_t)n * G_ * M_;
#pragma unroll
    for (int gp = 0; gp < 8; gp++) {
        float x0, y0, x1, y1;
        unpack2(acc0[gp], x0, y0);
        unpack2(acc1[gp], x1, y1);
        g_w[base + (size_t)(2*gp)   * M_ + m0] = fmaxf(x0, 0.0f) + 1e-6f;
        g_w[base + (size_t)(2*gp+1) * M_ + m0] = fmaxf(y0, 0.0f) + 1e-6f;
        g_w[base + (size_t)(2*gp)   * M_ + m1] = fmaxf(x1, 0.0f) + 1e-6f;
        g_w[base + (size_t)(2*gp+1) * M_ + m1] = fmaxf(y1, 0.0f) + 1e-6f;
    }
}

// ---------------- flash: QK 2-product (q hi only), PV 3-product ----------------
#define FQ_H 0
#define FSTG 16384
#define FS_KH 0
#define FS_KL 8192
#define FS_VH 16384
#define FS_VL 24576
#define FSTG_BYTES 32768
#define FLASH_SMEM (16384 + 2 * 32768)   // 81920

__global__ __launch_bounds__(256, 2) void flash_kernel() {
    extern __shared__ char smem[];
    const uint32_t sb = smem_to_u32(smem);
    const int t = threadIdx.x;
    const int wid = t >> 5, lane = t & 31;
    const int lr = lane & 7, lq = lane >> 3;
    const int gid = lane >> 2, tig = lane & 3;
    const int g = blockIdx.y;
    const int n0 = blockIdx.x * 128;
    const int z = blockIdx.z;

    const uint32_t a_off0 = (uint32_t)((wid*16 + (lq & 1)*8 + lr) * 128 + (lq >> 1) * 16);
    const uint32_t b_off0 = (uint32_t)(lr * 128 + (lq & 1) * 16);

    // load q tile (128n x 64d, hi only)
    {
        int row = t >> 1;
#pragma unroll
        for (int uu = 0; uu < 4; uu++) {
            int u = (t & 1) * 4 + uu;
            uint32_t so = SWZ((uint32_t)(row * 128 + u * 16));
            cp16(sb + FQ_H + so, g_qbH + ((size_t)(n0 + row) * 1024 + g * 64 + u * 8));
        }
    }
    auto loadStage = [&](int it, int stg) {
        const uint32_t sbase = sb + FSTG + stg * FSTG_BYTES;
        const int m0 = z * 512 + it * 64;
        int row = t >> 2;
#pragma unroll
        for (int uu = 0; uu < 2; uu++) {
            int u = (t & 3) * 2 + uu;
            uint32_t so = SWZ((uint32_t)(row * 128 + u * 16));
            cp16(sbase + FS_KH + so, g_kbH + ((size_t)(m0 + row) * 1024 + g * 64 + u * 8));
            cp16(sbase + FS_KL + so, g_kbL + ((size_t)(m0 + row) * 1024 + g * 64 + u * 8));
            cp16(sbase + FS_VH + so, g_vtH + ((size_t)(g * 64 + row) * 1024 + m0 + u * 8));
            cp16(sbase + FS_VL + so, g_vtL + ((size_t)(g * 64 + row) * 1024 + m0 + u * 8));
        }
    };

    loadStage(0, 0);
    CP_COMMIT();

    float o_[8][4];
#pragma unroll
    for (int a = 0; a < 8; a++)
#pragma unroll
        for (int b = 0; b < 4; b++) o_[a][b] = 0.0f;
    float lr0 = 0.0f, lr1 = 0.0f;

    for (int it = 0; it < 8; it++) {
        if (it + 1 < 8) {
            loadStage(it + 1, (it + 1) & 1);
            CP_COMMIT();
            asm volatile("cp.async.wait_group 1;" ::: "memory");
        } else {
            asm volatile("cp.async.wait_group 0;" ::: "memory");
        }
        __syncthreads();

        const uint32_t st = sb + FSTG + (it & 1) * FSTG_BYTES;
        const int m0 = z * 512 + it * 64;

        // S = q.k^T : qh*kh + qh*kl
        float s[8][4];
#pragma unroll
        for (int a = 0; a < 8; a++)
#pragma unroll
            for (int b = 0; b < 4; b++) s[a][b] = 0.0f;

#pragma unroll
        for (int dc = 0; dc < 4; dc++) {
            uint32_t aoff = SWZ(a_off0 + (uint32_t)(dc * 32));
            uint32_t aqh[4];
            ldsm_x4(aqh, sb + FQ_H + aoff);
#pragma unroll
            for (int mt = 0; mt < 8; mt++) {
                uint32_t boff = SWZ(b_off0 + (uint32_t)(mt * 8 * 128 + dc * 32));
                uint32_t bkh[2], bkl[2];
                ldsm_x2(bkh, st + FS_KH + boff);
                ldsm_x2(bkl, st + FS_KL + boff);
                mma16816(s[mt], aqh, bkh);
                mma16816(s[mt], aqh, bkl);
            }
        }

        // softmax numerators -> P bf16 hi/lo A-fragments
        uint32_t paH[4][4], paL[4][4];
        const size_t wbase0 = ((size_t)(n0 + wid * 16 + gid) * G_ + g) * M_;
        const size_t wbase1 = wbase0 + (size_t)8 * G_ * M_;
#pragma unroll
        for (int mt = 0; mt < 8; mt++) {
            int mcol = m0 + mt * 8 + 2 * tig;
            float2 w0 = *(const float2*)&g_w[wbase0 + mcol];
            float2 w1 = *(const float2*)&g_w[wbase1 + mcol];
            float p0 = w0.x * fast_exp(s[mt][0] * 0.125f);
            float p1 = w0.y * fast_exp(s[mt][1] * 0.125f);
            float p2 = w1.x * fast_exp(s[mt][2] * 0.125f);
            float p3 = w1.y * fast_exp(s[mt][3] * 0.125f);
            lr0 += p0 + p1;
            lr1 += p2 + p3;
            uint32_t h01 = cvt2bf(p0, p1), h23 = cvt2bf(p2, p3);
            float l0 = p0 - bflo(h01), l1 = p1 - bfhi(h01);
            float l2 = p2 - bflo(h23), l3 = p3 - bfhi(h23);
            int kc = mt >> 1, hf = (mt & 1) * 2;
            paH[kc][hf + 0] = h01;
            paH[kc][hf + 1] = h23;
            paL[kc][hf + 0] = cvt2bf(l0, l1);
            paL[kc][hf + 1] = cvt2bf(l2, l3);
        }

        // out += P . V (hi/lo, drop lo*lo)
#pragma unroll
        for (int kc = 0; kc < 4; kc++) {
#pragma unroll
            for (int ot = 0; ot < 8; ot++) {
                uint32_t boff = SWZ(b_off0 + (uint32_t)(ot * 8 * 128 + kc * 32));
                uint32_t bvh[2], bvl[2];
                ldsm_x2(bvh, st + FS_VH + boff);
                ldsm_x2(bvl, st + FS_VL + boff);
                mma16816(o_[ot], paH[kc], bvh);
                mma16816(o_[ot], paH[kc], bvl);
                mma16816(o_[ot], paL[kc], bvh);
            }
        }
        __syncthreads();
    }

    lr0 += __shfl_xor_sync(0xffffffffu, lr0, 1);
    lr0 += __shfl_xor_sync(0xffffffffu, lr0, 2);
    lr1 += __shfl_xor_sync(0xffffffffu, lr1, 1);
    lr1 += __shfl_xor_sync(0xffffffffu, lr1, 2);

    const int r0 = n0 + wid * 16 + gid;
    if (tig == 0) {
        g_pl[z][(size_t)r0 * G_ + g] = lr0;
        g_pl[z][(size_t)(r0 + 8) * G_ + g] = lr1;
    }
#pragma unroll
    for (int ot = 0; ot < 8; ot++) {
        int col = g * 64 + ot * 8 + 2 * tig;
        *(float2*)&g_pacc[z][(size_t)r0 * D_ + col] = make_float2(o_[ot][0], o_[ot][1]);
        *(float2*)&g_pacc[z][(size_t)(r0 + 8) * D_ + col] = make_float2(o_[ot][2], o_[ot][3]);
    }
}

// ---------------- combine partials ----------------
__global__ __launch_bounds__(256) void reduce_kernel(const float* __restrict__ bv,
                                                     float* __restrict__ out) {
    int idx = blockIdx.x * 256 + threadIdx.x;
    int n = idx >> 8;
    int col = (idx & 255) << 2;
    int g = col >> 6;
    float l = 0.0f;
    float4 a = make_float4(0.f, 0.f, 0.f, 0.f);
#pragma unroll
    for (int zz = 0; zz < SPLITS; zz++) {
        l += g_pl[zz][(size_t)n * G_ + g];
        float4 p = *(const float4*)&g_pacc[zz][(size_t)n * D_ + col];
        a.x += p.x; a.y += p.y; a.z += p.z; a.w += p.w;
    }
    float inv = 1.0f / l;
    float4 b4 = *(const float4*)&bv[col];
    float4 o;
    o.x = fmaf(a.x, inv, b4.x);
    o.y = fmaf(a.y, inv, b4.y);
    o.z = fmaf(a.z, inv, b4.z);
    o.w = fmaf(a.w, inv, b4.w);
    *(float4*)&out[(size_t)n * D_ + col] = o;
}

// ---------------- host launcher: two independent chains on two streams ----------------
extern "C" void kernel_launch(void* const* d_in, const int* in_sizes, int n_in,
                              void* d_out, int out_size) {
    const float* roi   = (const float*)d_in[0];
    const float* ref   = (const float*)d_in[1];
    const float* rois1 = (const float*)d_in[2];
    const float* rois2 = (const float*)d_in[3];
    const float* Wq    = (const float*)d_in[4];
    const float* bq    = (const float*)d_in[5];
    const float* Wk    = (const float*)d_in[6];
    const float* bk    = (const float*)d_in[7];
    const float* Wg    = (const float*)d_in[8];
    const float* bg    = (const float*)d_in[9];
    const float* Wv    = (const float*)d_in[10];
    const float* bv    = (const float*)d_in[11];
    float* out = (float*)d_out;

    static cudaStream_t s2 = nullptr;
    static cudaEvent_t evFork = nullptr, evJoin = nullptr;
    static bool init_done = false;
    if (!init_done) {
        cudaFuncSetAttribute(flash_kernel, cudaFuncAttributeMaxDynamicSharedMemorySize, FLASH_SMEM);
        cudaFuncSetAttribute(tc_gemm, cudaFuncAttributeMaxDynamicSharedMemorySize, TC_SMEM);
        cudaStreamCreateWithFlags(&s2, cudaStreamNonBlocking);
        cudaEventCreateWithFlags(&evFork, cudaEventDisableTiming);
        cudaEventCreateWithFlags(&evJoin, cudaEventDisableTiming);
        init_done = true;
    }

    // fork: side chain (box_prep -> posw) on s2
    cudaEventRecord(evFork, 0);
    cudaStreamWaitEvent(s2, evFork, 0);
    box_prep<<<4, 256, 0, s2>>>(rois1, rois2);
    posw_kernel<<<dim3(2, 1024), 256, 0, s2>>>(Wg, bg);
    cudaEventRecord(evJoin, s2);

    // main chain: conv -> tc_gemm on default stream
    conv_a<<<dim3(1024, 3), 256>>>(roi, ref, Wv);
    conv_w<<<dim3(16, 16, 2), 256>>>(Wq, Wk);
    tc_gemm<<<dim3(16, 8, 3), 256, TC_SMEM>>>(bq, bk);

    // join, then flash + reduce
    cudaStreamWaitEvent(0, evJoin, 0);
    flash_kernel<<<dim3(8, 16, 2), 256, FLASH_SMEM>>>();
    reduce_kernel<<<1024, 256>>>(bv, out);
}

// round 17
// speedup vs baseline: 1.3418x; 1.0204x over previous
#include <cuda_runtime.h>
#include <cuda_bf16.h>
#include <math.h>
#include <stdint.h>

#define N_ 1024
#define M_ 1024
#define D_ 1024
#define G_ 16
#define DG_ 64
#define SPLITS 2

typedef unsigned long long u64;

// ---------------- scratch ----------------
__device__ float g_w[(size_t)N_ * G_ * M_];      // (N, G, M)
__device__ float g_boxA[N_ * 4];
__device__ float g_boxB[M_ * 4];
__device__ float g_trigA[N_ * 32];
__device__ float g_trigBt[32 * M_];
__device__ float g_pacc[SPLITS][(size_t)N_ * D_];
__device__ float g_pl[SPLITS][(size_t)N_ * G_];

// bf16 hi/lo operand buffers
#define MEG (1024 * 1024)
__device__ __align__(16) uint16_t g_roiH[MEG], g_roiL[MEG];
__device__ __align__(16) uint16_t g_refH[MEG], g_refL[MEG];
__device__ __align__(16) uint16_t g_wvH[MEG],  g_wvL[MEG];
__device__ __align__(16) uint16_t g_wqtH[MEG], g_wqtL[MEG];   // Wq^T [j][k]
__device__ __align__(16) uint16_t g_wktH[MEG], g_wktL[MEG];   // Wk^T [j][k]
// GEMM outputs (bf16), MMA-ready layouts for flash
__device__ __align__(16) uint16_t g_qbH[MEG];                 // q [n][d] (hi only)
__device__ __align__(16) uint16_t g_kbH[MEG], g_kbL[MEG];     // k [m][d]
__device__ __align__(16) uint16_t g_vtH[MEG], g_vtL[MEG];     // v^T [o][m]

// ---------------- f32x2 helpers ----------------
__device__ __forceinline__ void fma2(u64& d, u64 a, u64 b) {
    asm("fma.rn.f32x2 %0, %1, %2, %0;" : "+l"(d) : "l"(a), "l"(b));
}
__device__ __forceinline__ u64 pack2(float x, float y) {
    u64 r;
    asm("mov.b64 %0, {%1, %2};" : "=l"(r) : "f"(x), "f"(y));
    return r;
}
__device__ __forceinline__ void unpack2(u64 p, float& x, float& y) {
    asm("mov.b64 {%0, %1}, %2;" : "=f"(x), "=f"(y) : "l"(p));
}
__device__ __forceinline__ u64 dup2(float x) { return pack2(x, x); }

__device__ __forceinline__ float fast_exp(float x) {
    float t = x * 1.4426950408889634f;
    t = fminf(fmaxf(t, -120.0f), 120.0f);
    float fi = floorf(t);
    float f = t - fi;
    float p = 1.5403530393e-4f;
    p = fmaf(p, f, 1.3333558146e-3f);
    p = fmaf(p, f, 9.6181291076e-3f);
    p = fmaf(p, f, 5.5504108664e-2f);
    p = fmaf(p, f, 2.4022650696e-1f);
    p = fmaf(p, f, 6.9314718056e-1f);
    p = fmaf(p, f, 1.0f);
    return p * __int_as_float(((int)fi + 127) << 23);
}

__constant__ float c_cf[8] = {100.0f, 42.169650f, 17.782794f, 7.4989421f,
                              3.1622776f, 1.3335214f, 0.56234133f, 0.23713737f};

// ---------------- mma / bf16 helpers (baseline PTX) ----------------
__device__ __forceinline__ uint32_t smem_to_u32(const void* p) {
    uint32_t a;
    asm("{ .reg .u64 t; cvta.to.shared.u64 t, %1; cvt.u32.u64 %0, t; }" : "=r"(a) : "l"(p));
    return a;
}
__device__ __forceinline__ void mma16816(float* d, const uint32_t* a, const uint32_t* b) {
    asm volatile(
        "mma.sync.aligned.m16n8k16.row.col.f32.bf16.bf16.f32 "
        "{%0,%1,%2,%3}, {%4,%5,%6,%7}, {%8,%9}, {%0,%1,%2,%3};"
        : "+f"(d[0]), "+f"(d[1]), "+f"(d[2]), "+f"(d[3])
        : "r"(a[0]), "r"(a[1]), "r"(a[2]), "r"(a[3]), "r"(b[0]), "r"(b[1]));
}
__device__ __forceinline__ void ldsm_x4(uint32_t* r, uint32_t addr) {
    asm volatile("ldmatrix.sync.aligned.m8n8.x4.shared.b16 {%0,%1,%2,%3}, [%4];"
                 : "=r"(r[0]), "=r"(r[1]), "=r"(r[2]), "=r"(r[3]) : "r"(addr));
}
__device__ __forceinline__ void ldsm_x2(uint32_t* r, uint32_t addr) {
    asm volatile("ldmatrix.sync.aligned.m8n8.x2.shared.b16 {%0,%1}, [%2];"
                 : "=r"(r[0]), "=r"(r[1]) : "r"(addr));
}
__device__ __forceinline__ void cp16(uint32_t saddr, const void* gptr) {
    asm volatile("cp.async.cg.shared.global [%0], [%1], 16;" :: "r"(saddr), "l"(gptr));
}
#define CP_COMMIT() asm volatile("cp.async.commit_group;" ::: "memory")
#define SWZ(bo) ((bo) ^ (((bo) >> 3) & 0x70))

// pack (lo, hi) floats -> bf16x2 register (lo in bits [0:16))
__device__ __forceinline__ uint32_t cvt2bf(float lo, float hi) {
    uint32_t r;
    asm("cvt.rn.satfinite.bf16x2.f32 %0, %1, %2;" : "=r"(r) : "f"(hi), "f"(lo));
    return r;
}
__device__ __forceinline__ float bflo(uint32_t p) { return __uint_as_float(p << 16); }
__device__ __forceinline__ float bfhi(uint32_t p) { return __uint_as_float(p & 0xFFFF0000u); }

// ---------------- box prep ----------------
__global__ void box_prep(const float* __restrict__ rois1, const float* __restrict__ rois2) {
    int i = blockIdx.x * blockDim.x + threadIdx.x;
    if (i >= N_) return;
    {
        float xmin = rois1[i*4+0], ymin = rois1[i*4+1], xmax = rois1[i*4+2], ymax = rois1[i*4+3];
        float w = xmax - xmin + 1.0f, h = ymax - ymin + 1.0f;
        g_boxA[i*4+0] = 0.5f*(xmin+xmax); g_boxA[i*4+1] = 0.5f*(ymin+ymax);
        g_boxA[i*4+2] = 1.0f/w;           g_boxA[i*4+3] = 1.0f/h;
        float lw = logf(w), lh = logf(h);
#pragma unroll
        for (int f = 0; f < 8; f++) {
            float s, c;
            sincosf(lw * c_cf[f], &s, &c);
            g_trigA[i*32 + f] = s;      g_trigA[i*32 + 8 + f] = c;
            sincosf(lh * c_cf[f], &s, &c);
            g_trigA[i*32 + 16 + f] = s; g_trigA[i*32 + 24 + f] = c;
        }
    }
    {
        float xmin = rois2[i*4+0], ymin = rois2[i*4+1], xmax = rois2[i*4+2], ymax = rois2[i*4+3];
        float w = xmax - xmin + 1.0f, h = ymax - ymin + 1.0f;
        g_boxB[i*4+0] = 0.5f*(xmin+xmax); g_boxB[i*4+1] = 0.5f*(ymin+ymax);
        g_boxB[i*4+2] = 1.0f/w;           g_boxB[i*4+3] = 1.0f/h;
        float lw = logf(w), lh = logf(h);
#pragma unroll
        for (int f = 0; f < 8; f++) {
            float s, c;
            sincosf(lw * c_cf[f], &s, &c);
            g_trigBt[f*M_ + i] = s;        g_trigBt[(8+f)*M_ + i] = c;
            sincosf(lh * c_cf[f], &s, &c);
            g_trigBt[(16+f)*M_ + i] = s;   g_trigBt[(24+f)*M_ + i] = c;
        }
    }
}

// ---------------- fp32 -> bf16 hi/lo (row-major tensors) ----------------
__global__ __launch_bounds__(256) void conv_a(const float* __restrict__ roi,
                                              const float* __restrict__ ref,
                                              const float* __restrict__ wv) {
    const int z = blockIdx.y;
    const float4* src = (const float4*)(z == 0 ? roi : z == 1 ? ref : wv);
    uint2* dh = (uint2*)(z == 0 ? g_roiH : z == 1 ? g_refH : g_wvH);
    uint2* dl = (uint2*)(z == 0 ? g_roiL : z == 1 ? g_refL : g_wvL);
    int i = blockIdx.x * 256 + threadIdx.x;
    float4 x = src[i];
    uint32_t h01 = cvt2bf(x.x, x.y), h23 = cvt2bf(x.z, x.w);
    float l0 = x.x - bflo(h01), l1 = x.y - bfhi(h01);
    float l2 = x.z - bflo(h23), l3 = x.w - bfhi(h23);
    dh[i] = make_uint2(h01, h23);
    dl[i] = make_uint2(cvt2bf(l0, l1), cvt2bf(l2, l3));
}

// ---------------- Wq/Wk transpose + bf16 hi/lo: W[k][j] -> Wt[j][k] ----------------
__global__ __launch_bounds__(256) void conv_w(const float* __restrict__ Wq,
                                              const float* __restrict__ Wk) {
    __shared__ float ts[64][65];
    const int z = blockIdx.z;
    const float* W = z ? Wk : Wq;
    uint2* dh = (uint2*)(z ? g_wktH : g_wqtH);
    uint2* dl = (uint2*)(z ? g_wktL : g_wqtL);
    const int j0 = blockIdx.x * 64, k0 = blockIdx.y * 64;
    const int t = threadIdx.x;
#pragma unroll
    for (int it = 0; it < 4; it++) {
        int lin = it * 256 + t;
        int k = lin >> 4, j4 = (lin & 15) << 2;
        float4 v = *(const float4*)&W[(size_t)(k0 + k) * D_ + j0 + j4];
        ts[j4 + 0][k] = v.x; ts[j4 + 1][k] = v.y; ts[j4 + 2][k] = v.z; ts[j4 + 3][k] = v.w;
    }
    __syncthreads();
#pragma unroll
    for (int it = 0; it < 4; it++) {
        int lin = it * 256 + t;
        int j = lin >> 4, k4 = (lin & 15) << 2;
        float a = ts[j][k4 + 0], b = ts[j][k4 + 1], c = ts[j][k4 + 2], d = ts[j][k4 + 3];
        uint32_t h01 = cvt2bf(a, b), h23 = cvt2bf(c, d);
        float l0 = a - bflo(h01), l1 = b - bfhi(h01);
        float l2 = c - bflo(h23), l3 = d - bfhi(h23);
        size_t idx = ((size_t)(j0 + j) * D_ + k0 + k4) >> 2;
        dh[idx] = make_uint2(h01, h23);
        dl[idx] = make_uint2(cvt2bf(l0, l1), cvt2bf(l2, l3));
    }
}

// ---------------- tensor-core GEMM: 128m x 64n tiles, full 3-product ----------------
#define OFF_AH 0
#define OFF_AL 16384
#define OFF_BH 32768
#define OFF_BL 40960
#define STAGE_BYTES 49152
#define TC_SMEM (2 * STAGE_BYTES)   // 98304

__global__ __launch_bounds__(256, 2) void tc_gemm(const float* __restrict__ bq,
                                                  const float* __restrict__ bk) {
    extern __shared__ char smem[];
    const uint32_t sb = smem_to_u32(smem);
    const int t = threadIdx.x;
    const int wid = t >> 5, lane = t & 31;
    const int j0 = blockIdx.x * 64, i0 = blockIdx.y * 128;
    const int mat = blockIdx.z;

    const uint16_t* Ah;
    const uint16_t* Al;
    const uint16_t* Bh;
    const uint16_t* Bl;
    if (mat == 0)      { Ah = g_roiH; Al = g_roiL; Bh = g_wqtH; Bl = g_wqtL; }
    else if (mat == 1) { Ah = g_refH; Al = g_refL; Bh = g_wktH; Bl = g_wktL; }
    else               { Ah = g_refH; Al = g_refL; Bh = g_wvH;  Bl = g_wvL; }

    const int wm = wid & 3, wn = wid >> 2;
    const int lr = lane & 7, lq = lane >> 3;

    float d[2][4][4];
#pragma unroll
    for (int a = 0; a < 2; a++)
#pragma unroll
        for (int b = 0; b < 4; b++)
#pragma unroll
            for (int c = 0; c < 4; c++) d[a][b][c] = 0.0f;

    const uint32_t a_off0 = (uint32_t)((wm*32 + (lq & 1)*8 + lr) * 128 + (lq >> 1) * 16);
    const uint32_t b_off0 = (uint32_t)((wn*32 + lr) * 128 + (lq & 1) * 16);

    auto loadChunk = [&](int ch, int stage) {
        const uint32_t sbase = sb + stage * STAGE_BYTES;
        {
            int row = t >> 1;
#pragma unroll
            for (int uu = 0; uu < 4; uu++) {
                int u = (t & 1) * 4 + uu;
                uint32_t so = SWZ((uint32_t)(row * 128 + u * 16));
                cp16(sbase + OFF_AH + so, Ah + ((size_t)(i0 + row) * 1024 + ch * 64 + u * 8));
                cp16(sbase + OFF_AL + so, Al + ((size_t)(i0 + row) * 1024 + ch * 64 + u * 8));
            }
        }
        {
            int row = t >> 2;
#pragma unroll
            for (int uu = 0; uu < 2; uu++) {
                int u = (t & 3) * 2 + uu;
                uint32_t so = SWZ((uint32_t)(row * 128 + u * 16));
                cp16(sbase + OFF_BH + so, Bh + ((size_t)(j0 + row) * 1024 + ch * 64 + u * 8));
                cp16(sbase + OFF_BL + so, Bl + ((size_t)(j0 + row) * 1024 + ch * 64 + u * 8));
            }
        }
    };

    loadChunk(0, 0);
    CP_COMMIT();

    for (int ch = 0; ch < 16; ch++) {
        if (ch + 1 < 16) {
            loadChunk(ch + 1, (ch + 1) & 1);
            CP_COMMIT();
            asm volatile("cp.async.wait_group 1;" ::: "memory");
        } else {
            asm volatile("cp.async.wait_group 0;" ::: "memory");
        }
        __syncthreads();

        const uint32_t st = sb + (ch & 1) * STAGE_BYTES;
#pragma unroll
        for (int ks = 0; ks < 4; ks++) {
            const uint32_t kb = (uint32_t)(ks * 32);
            uint32_t ah[2][4], al[2][4], bh[4][2], bl[4][2];
#pragma unroll
            for (int ma = 0; ma < 2; ma++) {
                uint32_t off = SWZ(a_off0 + (uint32_t)(ma * 16 * 128) + kb);
                ldsm_x4(ah[ma], st + OFF_AH + off);
                ldsm_x4(al[ma], st + OFF_AL + off);
            }
#pragma unroll
            for (int na = 0; na < 4; na++) {
                uint32_t off = SWZ(b_off0 + (uint32_t)(na * 8 * 128) + kb);
                ldsm_x2(bh[na], st + OFF_BH + off);
                ldsm_x2(bl[na], st + OFF_BL + off);
            }
#pragma unroll
            for (int ma = 0; ma < 2; ma++)
#pragma unroll
                for (int na = 0; na < 4; na++)
                    mma16816(d[ma][na], ah[ma], bh[na]);
#pragma unroll
            for (int ma = 0; ma < 2; ma++)
#pragma unroll
                for (int na = 0; na < 4; na++)
                    mma16816(d[ma][na], ah[ma], bl[na]);
#pragma unroll
            for (int ma = 0; ma < 2; ma++)
#pragma unroll
                for (int na = 0; na < 4; na++)
                    mma16816(d[ma][na], al[ma], bh[na]);
        }
        __syncthreads();
    }

    // stage D in smem: sd[128 i][68] cols j
    float* sd = (float*)smem;
    const int gid = lane >> 2, tig = lane & 3;
#pragma unroll
    for (int ma = 0; ma < 2; ma++)
#pragma unroll
        for (int na = 0; na < 4; na++) {
            int row = wm * 32 + ma * 16 + gid;
            int col = wn * 32 + na * 8 + 2 * tig;
            sd[row * 68 + col]           = d[ma][na][0];
            sd[row * 68 + col + 1]       = d[ma][na][1];
            sd[(row + 8) * 68 + col]     = d[ma][na][2];
            sd[(row + 8) * 68 + col + 1] = d[ma][na][3];
        }
    __syncthreads();

    if (mat == 0) {
        int i = t >> 1, jh = (t & 1) * 32;
#pragma unroll
        for (int jj = 0; jj < 32; jj += 4) {
            float4 v = *(const float4*)&sd[i * 68 + jh + jj];
            float4 bb = *(const float4*)&bq[j0 + jh + jj];
            v.x += bb.x; v.y += bb.y; v.z += bb.z; v.w += bb.w;
            uint32_t h01 = cvt2bf(v.x, v.y), h23 = cvt2bf(v.z, v.w);
            size_t off = (size_t)(i0 + i) * 1024 + j0 + jh + jj;
            *(uint2*)&g_qbH[off] = make_uint2(h01, h23);
        }
    } else if (mat == 1) {
        int i = t >> 1, jh = (t & 1) * 32;
#pragma unroll
        for (int jj = 0; jj < 32; jj += 4) {
            float4 v = *(const float4*)&sd[i * 68 + jh + jj];
            float4 bb = *(const float4*)&bk[j0 + jh + jj];
            v.x += bb.x; v.y += bb.y; v.z += bb.z; v.w += bb.w;
            uint32_t h01 = cvt2bf(v.x, v.y), h23 = cvt2bf(v.z, v.w);
            float l0 = v.x - bflo(h01), l1 = v.y - bfhi(h01);
            float l2 = v.z - bflo(h23), l3 = v.w - bfhi(h23);
            size_t off = (size_t)(i0 + i) * 1024 + j0 + jh + jj;
            *(uint2*)&g_kbH[off] = make_uint2(h01, h23);
            *(uint2*)&g_kbL[off] = make_uint2(cvt2bf(l0, l1), cvt2bf(l2, l3));
        }
    } else {
        int j = t >> 2, ih = (t & 3) * 32;
#pragma unroll
        for (int mm = 0; mm < 32; mm += 4) {
            float v0 = sd[(ih + mm + 0) * 68 + j];
            float v1 = sd[(ih + mm + 1) * 68 + j];
            float v2 = sd[(ih + mm + 2) * 68 + j];
            float v3 = sd[(ih + mm + 3) * 68 + j];
            uint32_t h01 = cvt2bf(v0, v1), h23 = cvt2bf(v2, v3);
            float l0 = v0 - bflo(h01), l1 = v1 - bfhi(h01);
            float l2 = v2 - bflo(h23), l3 = v3 - bfhi(h23);
            size_t off = (size_t)(j0 + j) * 1024 + i0 + ih + mm;
            *(uint2*)&g_vtH[off] = make_uint2(h01, h23);
            *(uint2*)&g_vtL[off] = make_uint2(cvt2bf(l0, l1), cvt2bf(l2, l3));
        }
    }
}

// ---------------- position-weight kernel: 4 m per thread ----------------
// grid (1, 1024): thread t handles m = t, t+256, t+512, t+768 for row n = blockIdx.y.
__global__ __launch_bounds__(256, 2) void posw_kernel(const float* __restrict__ Wg,
                                                      const float* __restrict__ bg) {
    __shared__ float wgt[64][16];
    __shared__ float bgs[G_];
    const int t = threadIdx.x;
#pragma unroll
    for (int i = t; i < 1024; i += 256) {
        int g = i >> 6, e = i & 63;
        wgt[e][g] = Wg[i];
    }
    if (t < G_) bgs[t] = bg[t];
    __syncthreads();

    const int n = blockIdx.y;
    const int m0 = t, m1 = t + 256, m2 = t + 512, m3 = t + 768;

    u64 acc[4][8];
#pragma unroll
    for (int gp = 0; gp < 8; gp++) {
        u64 b2 = pack2(bgs[2*gp], bgs[2*gp+1]);
        acc[0][gp] = b2; acc[1][gp] = b2; acc[2][gp] = b2; acc[3][gp] = b2;
    }

    // update all 4 m's accumulators for embedding element e
    auto upd = [&](int e, float v0, float v1, float v2, float v3) {
        const ulonglong2* wr = (const ulonglong2*)&wgt[e][0];
        ulonglong2 wa = wr[0], wb = wr[1];
        u64 d0 = dup2(v0), d1 = dup2(v1), d2 = dup2(v2), d3 = dup2(v3);
        fma2(acc[0][0], d0, wa.x); fma2(acc[1][0], d1, wa.x); fma2(acc[2][0], d2, wa.x); fma2(acc[3][0], d3, wa.x);
        fma2(acc[0][1], d0, wa.y); fma2(acc[1][1], d1, wa.y); fma2(acc[2][1], d2, wa.y); fma2(acc[3][1], d3, wa.y);
        fma2(acc[0][2], d0, wb.x); fma2(acc[1][2], d1, wb.x); fma2(acc[2][2], d2, wb.x); fma2(acc[3][2], d3, wb.x);
        fma2(acc[0][3], d0, wb.y); fma2(acc[1][3], d1, wb.y); fma2(acc[2][3], d2, wb.y); fma2(acc[3][3], d3, wb.y);
        ulonglong2 wc = wr[2], wd = wr[3];
        fma2(acc[0][4], d0, wc.x); fma2(acc[1][4], d1, wc.x); fma2(acc[2][4], d2, wc.x); fma2(acc[3][4], d3, wc.x);
        fma2(acc[0][5], d0, wc.y); fma2(acc[1][5], d1, wc.y); fma2(acc[2][5], d2, wc.y); fma2(acc[3][5], d3, wc.y);
        fma2(acc[0][6], d0, wd.x); fma2(acc[1][6], d1, wd.x); fma2(acc[2][6], d2, wd.x); fma2(acc[3][6], d3, wd.x);
        fma2(acc[0][7], d0, wd.y); fma2(acc[1][7], d1, wd.y); fma2(acc[2][7], d2, wd.y); fma2(acc[3][7], d3, wd.y);
    };

    const float4 bn = *(const float4*)&g_boxA[n * 4];
    const float4 bmA = *(const float4*)&g_boxB[m0 * 4];
    const float4 bmB = *(const float4*)&g_boxB[m1 * 4];
    const float4 bmC = *(const float4*)&g_boxB[m2 * 4];
    const float4 bmD = *(const float4*)&g_boxB[m3 * 4];

    // dx (e 0..15), dy (16..31): fast log + fast sincos per m
    {
        float px0 = __logf(fabsf(bn.x - bmA.x) * bn.z + 1e-3f);
        float px1 = __logf(fabsf(bn.x - bmB.x) * bn.z + 1e-3f);
        float px2 = __logf(fabsf(bn.x - bmC.x) * bn.z + 1e-3f);
        float px3 = __logf(fabsf(bn.x - bmD.x) * bn.z + 1e-3f);
#pragma unroll
        for (int f = 0; f < 8; f++) {
            float s0, c0, s1, c1, s2, c2, s3, c3;
            __sincosf(px0 * c_cf[f], &s0, &c0);
            __sincosf(px1 * c_cf[f], &s1, &c1);
            __sincosf(px2 * c_cf[f], &s2, &c2);
            __sincosf(px3 * c_cf[f], &s3, &c3);
            upd(f, s0, s1, s2, s3);
            upd(8 + f, c0, c1, c2, c3);
        }
        float py0 = __logf(fabsf(bn.y - bmA.y) * bn.w + 1e-3f);
        float py1 = __logf(fabsf(bn.y - bmB.y) * bn.w + 1e-3f);
        float py2 = __logf(fabsf(bn.y - bmC.y) * bn.w + 1e-3f);
        float py3 = __logf(fabsf(bn.y - bmD.y) * bn.w + 1e-3f);
#pragma unroll
        for (int f = 0; f < 8; f++) {
            float s0, c0, s1, c1, s2, c2, s3, c3;
            __sincosf(py0 * c_cf[f], &s0, &c0);
            __sincosf(py1 * c_cf[f], &s1, &c1);
            __sincosf(py2 * c_cf[f], &s2, &c2);
            __sincosf(py3 * c_cf[f], &s3, &c3);
            upd(16 + f, s0, s1, s2, s3);
            upd(24 + f, c0, c1, c2, c3);
        }
    }

    // dw (e 32..47): angle-difference; trigA shared across all 4 m
#pragma unroll
    for (int f = 0; f < 8; f++) {
        float snf = g_trigA[n*32 + f], cnf = g_trigA[n*32 + 8 + f];
        float s0 = g_trigBt[f*M_ + m0], c0 = g_trigBt[(8+f)*M_ + m0];
        float s1 = g_trigBt[f*M_ + m1], c1 = g_trigBt[(8+f)*M_ + m1];
        float s2 = g_trigBt[f*M_ + m2], c2 = g_trigBt[(8+f)*M_ + m2];
        float s3 = g_trigBt[f*M_ + m3], c3 = g_trigBt[(8+f)*M_ + m3];
        upd(32 + f, snf*c0 - cnf*s0, snf*c1 - cnf*s1, snf*c2 - cnf*s2, snf*c3 - cnf*s3);
        upd(40 + f, fmaf(cnf, c0, snf*s0), fmaf(cnf, c1, snf*s1),
                    fmaf(cnf, c2, snf*s2), fmaf(cnf, c3, snf*s3));
    }
    // dh (e 48..63)
#pragma unroll
    for (int f = 0; f < 8; f++) {
        float snf = g_trigA[n*32 + 16 + f], cnf = g_trigA[n*32 + 24 + f];
        float s0 = g_trigBt[(16+f)*M_ + m0], c0 = g_trigBt[(24+f)*M_ + m0];
        float s1 = g_trigBt[(16+f)*M_ + m1], c1 = g_trigBt[(24+f)*M_ + m1];
        float s2 = g_trigBt[(16+f)*M_ + m2], c2 = g_trigBt[(24+f)*M_ + m2];
        float s3 = g_trigBt[(16+f)*M_ + m3], c3 = g_trigBt[(24+f)*M_ + m3];
        upd(48 + f, snf*c0 - cnf*s0, snf*c1 - cnf*s1, snf*c2 - cnf*s2, snf*c3 - cnf*s3);
        upd(56 + f, fmaf(cnf, c0, snf*s0), fmaf(cnf, c1, snf*s1),
                    fmaf(cnf, c2, snf*s2), fmaf(cnf, c3, snf*s3));
    }

    const size_t base = (size_t)n * G_ * M_;
#pragma unroll
    for (int mi = 0; mi < 4; mi++) {
        const int m = t + mi * 256;
#pragma unroll
        for (int gp = 0; gp < 8; gp++) {
            float x, y;
            unpack2(acc[mi][gp], x, y);
            g_w[base + (size_t)(2*gp)   * M_ + m] = fmaxf(x, 0.0f) + 1e-6f;
            g_w[base + (size_t)(2*gp+1) * M_ + m] = fmaxf(y, 0.0f) + 1e-6f;
        }
    }
}

// ---------------- flash: QK 2-product (q hi only), PV 3-product ----------------
#define FQ_H 0
#define FSTG 16384
#define FS_KH 0
#define FS_KL 8192
#define FS_VH 16384
#define FS_VL 24576
#define FSTG_BYTES 32768
#define FLASH_SMEM (16384 + 2 * 32768)   // 81920

__global__ __launch_bounds__(256, 2) void flash_kernel() {
    extern __shared__ char smem[];
    const uint32_t sb = smem_to_u32(smem);
    const int t = threadIdx.x;
    const int wid = t >> 5, lane = t & 31;
    const int lr = lane & 7, lq = lane >> 3;
    const int gid = lane >> 2, tig = lane & 3;
    const int g = blockIdx.y;
    const int n0 = blockIdx.x * 128;
    const int z = blockIdx.z;

    const uint32_t a_off0 = (uint32_t)((wid*16 + (lq & 1)*8 + lr) * 128 + (lq >> 1) * 16);
    const uint32_t b_off0 = (uint32_t)(lr * 128 + (lq & 1) * 16);

    {
        int row = t >> 1;
#pragma unroll
        for (int uu = 0; uu < 4; uu++) {
            int u = (t & 1) * 4 + uu;
            uint32_t so = SWZ((uint32_t)(row * 128 + u * 16));
            cp16(sb + FQ_H + so, g_qbH + ((size_t)(n0 + row) * 1024 + g * 64 + u * 8));
        }
    }
    auto loadStage = [&](int it, int stg) {
        const uint32_t sbase = sb + FSTG + stg * FSTG_BYTES;
        const int m0 = z * 512 + it * 64;
        int row = t >> 2;
#pragma unroll
        for (int uu = 0; uu < 2; uu++) {
            int u = (t & 3) * 2 + uu;
            uint32_t so = SWZ((uint32_t)(row * 128 + u * 16));
            cp16(sbase + FS_KH + so, g_kbH + ((size_t)(m0 + row) * 1024 + g * 64 + u * 8));
            cp16(sbase + FS_KL + so, g_kbL + ((size_t)(m0 + row) * 1024 + g * 64 + u * 8));
            cp16(sbase + FS_VH + so, g_vtH + ((size_t)(g * 64 + row) * 1024 + m0 + u * 8));
            cp16(sbase + FS_VL + so, g_vtL + ((size_t)(g * 64 + row) * 1024 + m0 + u * 8));
        }
    };

    loadStage(0, 0);
    CP_COMMIT();

    float o_[8][4];
#pragma unroll
    for (int a = 0; a < 8; a++)
#pragma unroll
        for (int b = 0; b < 4; b++) o_[a][b] = 0.0f;
    float lr0 = 0.0f, lr1 = 0.0f;

    for (int it = 0; it < 8; it++) {
        if (it + 1 < 8) {
            loadStage(it + 1, (it + 1) & 1);
            CP_COMMIT();
            asm volatile("cp.async.wait_group 1;" ::: "memory");
        } else {
            asm volatile("cp.async.wait_group 0;" ::: "memory");
        }
        __syncthreads();

        const uint32_t st = sb + FSTG + (it & 1) * FSTG_BYTES;
        const int m0 = z * 512 + it * 64;

        // S = q.k^T : qh*kh + qh*kl
        float s[8][4];
#pragma unroll
        for (int a = 0; a < 8; a++)
#pragma unroll
            for (int b = 0; b < 4; b++) s[a][b] = 0.0f;

#pragma unroll
        for (int dc = 0; dc < 4; dc++) {
            uint32_t aoff = SWZ(a_off0 + (uint32_t)(dc * 32));
            uint32_t aqh[4];
            ldsm_x4(aqh, sb + FQ_H + aoff);
#pragma unroll
            for (int mt = 0; mt < 8; mt++) {
                uint32_t boff = SWZ(b_off0 + (uint32_t)(mt * 8 * 128 + dc * 32));
                uint32_t bkh[2], bkl[2];
                ldsm_x2(bkh, st + FS_KH + boff);
                ldsm_x2(bkl, st + FS_KL + boff);
                mma16816(s[mt], aqh, bkh);
                mma16816(s[mt], aqh, bkl);
            }
        }

        // softmax numerators -> P bf16 hi/lo A-fragments
        uint32_t paH[4][4], paL[4][4];
        const size_t wbase0 = ((size_t)(n0 + wid * 16 + gid) * G_ + g) * M_;
        const size_t wbase1 = wbase0 + (size_t)8 * G_ * M_;
#pragma unroll
        for (int mt = 0; mt < 8; mt++) {
            int mcol = m0 + mt * 8 + 2 * tig;
            float2 w0 = *(const float2*)&g_w[wbase0 + mcol];
            float2 w1 = *(const float2*)&g_w[wbase1 + mcol];
            float p0 = w0.x * fast_exp(s[mt][0] * 0.125f);
            float p1 = w0.y * fast_exp(s[mt][1] * 0.125f);
            float p2 = w1.x * fast_exp(s[mt][2] * 0.125f);
            float p3 = w1.y * fast_exp(s[mt][3] * 0.125f);
            lr0 += p0 + p1;
            lr1 += p2 + p3;
            uint32_t h01 = cvt2bf(p0, p1), h23 = cvt2bf(p2, p3);
            float l0 = p0 - bflo(h01), l1 = p1 - bfhi(h01);
            float l2 = p2 - bflo(h23), l3 = p3 - bfhi(h23);
            int kc = mt >> 1, hf = (mt & 1) * 2;
            paH[kc][hf + 0] = h01;
            paH[kc][hf + 1] = h23;
            paL[kc][hf + 0] = cvt2bf(l0, l1);
            paL[kc][hf + 1] = cvt2bf(l2, l3);
        }

        // out += P . V (hi/lo, drop lo*lo)
#pragma unroll
        for (int kc = 0; kc < 4; kc++) {
#pragma unroll
            for (int ot = 0; ot < 8; ot++) {
                uint32_t boff = SWZ(b_off0 + (uint32_t)(ot * 8 * 128 + kc * 32));
                uint32_t bvh[2], bvl[2];
                ldsm_x2(bvh, st + FS_VH + boff);
                ldsm_x2(bvl, st + FS_VL + boff);
                mma16816(o_[ot], paH[kc], bvh);
                mma16816(o_[ot], paH[kc], bvl);
                mma16816(o_[ot], paL[kc], bvh);
            }
        }
        __syncthreads();
    }

    lr0 += __shfl_xor_sync(0xffffffffu, lr0, 1);
    lr0 += __shfl_xor_sync(0xffffffffu, lr0, 2);
    lr1 += __shfl_xor_sync(0xffffffffu, lr1, 1);
    lr1 += __shfl_xor_sync(0xffffffffu, lr1, 2);

    const int r0 = n0 + wid * 16 + gid;
    if (tig == 0) {
        g_pl[z][(size_t)r0 * G_ + g] = lr0;
        g_pl[z][(size_t)(r0 + 8) * G_ + g] = lr1;
    }
#pragma unroll
    for (int ot = 0; ot < 8; ot++) {
        int col = g * 64 + ot * 8 + 2 * tig;
        *(float2*)&g_pacc[z][(size_t)r0 * D_ + col] = make_float2(o_[ot][0], o_[ot][1]);
        *(float2*)&g_pacc[z][(size_t)(r0 + 8) * D_ + col] = make_float2(o_[ot][2], o_[ot][3]);
    }
}

// ---------------- combine partials ----------------
__global__ __launch_bounds__(256) void reduce_kernel(const float* __restrict__ bv,
                                                     float* __restrict__ out) {
    int idx = blockIdx.x * 256 + threadIdx.x;
    int n = idx >> 8;
    int col = (idx & 255) << 2;
    int g = col >> 6;
    float l = 0.0f;
    float4 a = make_float4(0.f, 0.f, 0.f, 0.f);
#pragma unroll
    for (int zz = 0; zz < SPLITS; zz++) {
        l += g_pl[zz][(size_t)n * G_ + g];
        float4 p = *(const float4*)&g_pacc[zz][(size_t)n * D_ + col];
        a.x += p.x; a.y += p.y; a.z += p.z; a.w += p.w;
    }
    float inv = 1.0f / l;
    float4 b4 = *(const float4*)&bv[col];
    float4 o;
    o.x = fmaf(a.x, inv, b4.x);
    o.y = fmaf(a.y, inv, b4.y);
    o.z = fmaf(a.z, inv, b4.z);
    o.w = fmaf(a.w, inv, b4.w);
    *(float4*)&out[(size_t)n * D_ + col] = o;
}

// ---------------- host launcher: two independent chains on two streams ----------------
extern "C" void kernel_launch(void* const* d_in, const int* in_sizes, int n_in,
                              void* d_out, int out_size) {
    const float* roi   = (const float*)d_in[0];
    const float* ref   = (const float*)d_in[1];
    const float* rois1 = (const float*)d_in[2];
    const float* rois2 = (const float*)d_in[3];
    const float* Wq    = (const float*)d_in[4];
    const float* bq    = (const float*)d_in[5];
    const float* Wk    = (const float*)d_in[6];
    const float* bk    = (const float*)d_in[7];
    const float* Wg    = (const float*)d_in[8];
    const float* bg    = (const float*)d_in[9];
    const float* Wv    = (const float*)d_in[10];
    const float* bv    = (const float*)d_in[11];
    float* out = (float*)d_out;

    static cudaStream_t s2 = nullptr;
    static cudaEvent_t evFork = nullptr, evJoin = nullptr;
    static bool init_done = false;
    if (!init_done) {
        cudaFuncSetAttribute(flash_kernel, cudaFuncAttributeMaxDynamicSharedMemorySize, FLASH_SMEM);
        cudaFuncSetAttribute(tc_gemm, cudaFuncAttributeMaxDynamicSharedMemorySize, TC_SMEM);
        cudaStreamCreateWithFlags(&s2, cudaStreamNonBlocking);
        cudaEventCreateWithFlags(&evFork, cudaEventDisableTiming);
        cudaEventCreateWithFlags(&evJoin, cudaEventDisableTiming);
        init_done = true;
    }

    // fork: side chain (box_prep -> posw) on s2
    cudaEventRecord(evFork, 0);
    cudaStreamWaitEvent(s2, evFork, 0);
    box_prep<<<4, 256, 0, s2>>>(rois1, rois2);
    posw_kernel<<<dim3(1, 1024), 256, 0, s2>>>(Wg, bg);
    cudaEventRecord(evJoin, s2);

    // main chain: conv -> tc_gemm on default stream
    conv_a<<<dim3(1024, 3), 256>>>(roi, ref, Wv);
    conv_w<<<dim3(16, 16, 2), 256>>>(Wq, Wk);
    tc_gemm<<<dim3(16, 8, 3), 256, TC_SMEM>>>(bq, bk);

    // join, then flash + reduce
    cudaStreamWaitEvent(0, evJoin, 0);
    flash_kernel<<<dim3(8, 16, 2), 256, FLASH_SMEM>>>();
    reduce_kernel<<<1024, 256>>>(bv, out);
}